// round 9
// baseline (speedup 1.0000x reference)
#include <cuda_runtime.h>
#include <cuda_fp16.h>
#include <cstdint>

#define HID 256
#define NB 32
#define NS 8192

// SMEM byte offsets (main kernel)
#define SA_HI 0          // A hi plane: 128 rows x 512B (f16) = 64KB
#define SA_C  65536      // A fp8 concat plane: 128 rows x 512B = 64KB
#define SBH   131072     // B f16-hi double buffer: 2 x 16KB
#define SBC   163840     // B fp8 double buffer: 2 x 16KB
#define SCS   196608     // c[b,*] 1KB
#define SVS   197632     // v 1KB
#define SLOG  198656     // 128 rows x 2 slots floats
#define SES   199680     // 128 exp values
#define SRED  200192     // reduce scratch
#define SMEM_MAIN 200704

#define WSCALE 32.0f
#define INV_WSCALE 0.03125f
#define LO_SCALE 2048.0f
#define INV_LO_SCALE 4.8828125e-4f

__device__ float    g_c[NB * HID];
__device__ uint32_t g_whi[HID * 128];   // 32*We f16-hi, [k_out][h/2] f16x2
__device__ uint16_t g_wc[HID * 256];    // fp8 concat [n][k'=512B]: per seg [b_hi(16) | b_lo*2048(16)]
__device__ float    g_pctx[2048 * HID]; // per-tile unnormalized context
__device__ float    g_msum[2048 * 2];   // per-tile (max, sum_exp)

// ---------------- helpers ----------------
__device__ __forceinline__ uint32_t cvta_smem(const void* p) {
    uint32_t a;
    asm("{ .reg .u64 t; cvta.to.shared.u64 t, %1; cvt.u32.u64 %0, t; }" : "=r"(a) : "l"(p));
    return a;
}
// pack two floats -> f16x2 (low half = f16(x0), high half = f16(x1))
__device__ __forceinline__ uint32_t pack_f16(float x0, float x1) {
    uint32_t r;
    asm("cvt.rn.f16x2.f32 %0, %1, %2;" : "=r"(r) : "f"(x1), "f"(x0));
    return r;
}
// pack two floats -> e4m3x2 (low byte = e4m3(x0), high byte = e4m3(x1))
__device__ __forceinline__ uint16_t pack_e4m3(float x0, float x1) {
    uint16_t r;
    asm("cvt.rn.satfinite.e4m3x2.f32 %0, %1, %2;" : "=h"(r) : "f"(x1), "f"(x0));
    return r;
}
__device__ __forceinline__ float2 h22f2(uint32_t w) {
    __half2 h = *reinterpret_cast<__half2*>(&w);
    return __half22float2(h);
}
__device__ __forceinline__ uint32_t lds32(uint32_t a) {
    uint32_t r;
    asm("ld.shared.b32 %0, [%1];" : "=r"(r) : "r"(a));
    return r;
}
__device__ __forceinline__ void sts128(uint32_t a, uint32_t x, uint32_t y, uint32_t z, uint32_t w) {
    asm volatile("st.shared.v4.b32 [%0], {%1,%2,%3,%4};" :: "r"(a), "r"(x), "r"(y), "r"(z), "r"(w) : "memory");
}
__device__ __forceinline__ void cp_async16(uint32_t saddr, const void* gptr) {
    uint64_t g;
    asm("cvta.to.global.u64 %0, %1;" : "=l"(g) : "l"(gptr));
    asm volatile("cp.async.cg.shared.global [%0], [%1], 16;" :: "r"(saddr), "l"(g) : "memory");
}
// fp16 x fp16, fp32 accumulate
__device__ __forceinline__ void mma_f32(float* c,
        const uint32_t* a, uint32_t b0, uint32_t b1) {
    asm("mma.sync.aligned.m16n8k16.row.col.f32.f16.f16.f32 "
        "{%0,%1,%2,%3}, {%4,%5,%6,%7}, {%8,%9}, {%0,%1,%2,%3};"
        : "+f"(c[0]), "+f"(c[1]), "+f"(c[2]), "+f"(c[3])
        : "r"(a[0]), "r"(a[1]), "r"(a[2]), "r"(a[3]), "r"(b0), "r"(b1));
}
// e4m3 x e4m3 k32, fp32 accumulate (both correction terms in one MMA)
__device__ __forceinline__ void mma_fp8(float* c,
        const uint32_t* a, uint32_t b0, uint32_t b1) {
    asm("mma.sync.aligned.m16n8k32.row.col.f32.e4m3.e4m3.f32 "
        "{%0,%1,%2,%3}, {%4,%5,%6,%7}, {%8,%9}, {%0,%1,%2,%3};"
        : "+f"(c[0]), "+f"(c[1]), "+f"(c[2]), "+f"(c[3])
        : "r"(a[0]), "r"(a[1]), "r"(a[2]), "r"(a[3]), "r"(b0), "r"(b1));
}
#define LDM4(r, a) \
    asm volatile("ldmatrix.sync.aligned.m8n8.x4.shared.b16 {%0,%1,%2,%3}, [%4];" \
        : "=r"((r)[0]), "=r"((r)[1]), "=r"((r)[2]), "=r"((r)[3]) : "r"(a))

// ---------------------------------------------------------------------------
// prep: 32*We[k,h] -> f16 hi plane + fp8 concat plane
// fp8 row layout per seg j (h 16j..16j+15): bytes [32j,+16)=e4m3(b_hi),
// [32j+16,+16)=e4m3(b_lo*2048)
// ---------------------------------------------------------------------------
__global__ void prep_w_kernel(const float* __restrict__ W) {
    int idx = blockIdx.x * 256 + threadIdx.x;  // 0..32767
    int n = idx >> 7, wp = idx & 127;
    int hp = wp * 2;
    float x0 = WSCALE * W[n * 512 + 256 + hp];
    float x1 = WSCALE * W[n * 512 + 257 + hp];
    uint32_t hi = pack_f16(x0, x1);
    float2 f = h22f2(hi);
    g_whi[idx] = hi;
    int j = hp >> 4, pos = (hp & 15) >> 1;
    g_wc[n * 256 + j * 16 + pos]     = pack_e4m3(x0, x1);
    g_wc[n * 256 + j * 16 + 8 + pos] = pack_e4m3((x0 - f.x) * LO_SCALE,
                                                 (x1 - f.y) * LO_SCALE);
}

// ---------------------------------------------------------------------------
// c[b,k] = bias[k] + sum_h hidden[b,h] * W[k,h]
// ---------------------------------------------------------------------------
__global__ void compute_c_kernel(const float* __restrict__ hidden,
                                 const float* __restrict__ W,
                                 const float* __restrict__ bias) {
    __shared__ float hs[HID];
    int b = blockIdx.x;
    int k = threadIdx.x;
    hs[k] = hidden[b * HID + k];
    __syncthreads();
    float acc = bias[k];
    const float4* wr = (const float4*)(W + (size_t)k * (2 * HID));
#pragma unroll 8
    for (int h4 = 0; h4 < HID / 4; h4++) {
        float4 w = wr[h4];
        acc += w.x * hs[h4 * 4 + 0] + w.y * hs[h4 * 4 + 1]
             + w.z * hs[h4 * 4 + 2] + w.w * hs[h4 * 4 + 3];
    }
    g_c[b * HID + k] = acc;
}

// ---------------------------------------------------------------------------
// stream B chunk q (f16-hi 16KB + fp8 16KB) into buf q&1
// ---------------------------------------------------------------------------
__device__ __forceinline__ void issue_b(uint32_t S, int q, int t) {
    int p = q >> 2, cc = q & 3;
    uint32_t bufH = S + SBH + (uint32_t)(q & 1) * 16384u;
    uint32_t bufC = S + SBC + (uint32_t)(q & 1) * 16384u;
    int n  = t >> 1;
    int wq = (t & 1) * 16;
    const uint32_t* srcH = g_whi + (size_t)(p * 128 + n) * 128 + cc * 32 + wq;
    const uint8_t*  srcC = (const uint8_t*)g_wc
                         + (size_t)(p * 128 + n) * 512 + cc * 128 + (t & 1) * 64;
    uint32_t sz   = ((uint32_t)n & 7) << 2;
    uint32_t wrow = (uint32_t)n * 32;
#pragma unroll
    for (int j = 0; j < 4; j++) {
        uint32_t wc = (uint32_t)(wq + j * 4);
        uint32_t ad = (wrow + (wc ^ sz)) << 2;
        cp_async16(bufH + ad, srcH + j * 4);
        cp_async16(bufC + ad, srcC + j * 16);
    }
}

// ---------------------------------------------------------------------------
// Main fused kernel: logits + fused partial softmax-context.
// term1 fp16 MMA fp32acc; both corrections merged into one fp8 k32 MMA.
// ---------------------------------------------------------------------------
__global__ void __launch_bounds__(256, 1) main_mma_kernel(
    const float* __restrict__ enc, const float* __restrict__ v,
    float* __restrict__ attn)
{
    extern __shared__ char smem[];
    const uint32_t S = cvta_smem(smem);

    int t = threadIdx.x;
    int lane = t & 31, w = t >> 5;
    int grp = lane >> 2, tig = lane & 3;
    int mbase = (w & 3) * 32;
    int nb    = (w >> 2) * 64;

    int tile  = blockIdx.x;          // 0..2047
    int b     = tile >> 6;
    int tm    = (tile & 63) * 128;
    size_t rowbase = (size_t)b * NS + tm;

    // ldmatrix lane addressing
    int lrow   = lane & 15;
    uint32_t ghalfA = (uint32_t)(lane >> 4);
    uint32_t sA     = (uint32_t)(lrow & 7);
    uint32_t aBase0  = S + SA_HI + (uint32_t)(mbase + lrow) * 512u;
    uint32_t aBase1  = aBase0 + 16u * 512u;
    uint32_t aCBase0 = S + SA_C  + (uint32_t)(mbase + lrow) * 512u;
    uint32_t aCBase1 = aCBase0 + 16u * 512u;
    uint32_t ghalfB = (uint32_t)((lane >> 3) & 1);
    uint32_t sBl    = (uint32_t)(lane & 7);
    uint32_t bRow0  = ((uint32_t)(nb + (lane & 7) + ((lane >> 4) & 1) * 8)) * 128u;

    ((float*)(smem + SCS))[t] = g_c[b * HID + t];
    ((float*)(smem + SVS))[t] = v[t];
    ((float*)(smem + SLOG))[t] = 0.f;

    issue_b(S, 0, t);
    asm volatile("cp.async.commit_group;" ::: "memory");
    issue_b(S, 1, t);
    asm volatile("cp.async.commit_group;" ::: "memory");

    // ---- A load: f16-hi plane + fp8 concat plane ([a_lo*2048 | a_hi(fp8)]) ----
    {
        int row = t >> 1, half = t & 1;
        const float4* src = ((const float4*)(enc + (rowbase + (size_t)row) * HID)) + half * 32;
        uint32_t sz4   = ((uint32_t)row & 7) << 2;
        uint32_t aRowH = S + SA_HI + (uint32_t)row * 512u;
        uint32_t aRowC = S + SA_C  + (uint32_t)row * 512u;
#pragma unroll 2
        for (int s = 0; s < 8; s++) {
            float4 f0 = src[4 * s], f1 = src[4 * s + 1];
            float4 f2 = src[4 * s + 2], f3 = src[4 * s + 3];
            uint32_t h0 = pack_f16(f0.x, f0.y), h1 = pack_f16(f0.z, f0.w);
            uint32_t h2 = pack_f16(f1.x, f1.y), h3 = pack_f16(f1.z, f1.w);
            uint32_t h4 = pack_f16(f2.x, f2.y), h5 = pack_f16(f2.z, f2.w);
            uint32_t h6 = pack_f16(f3.x, f3.y), h7 = pack_f16(f3.z, f3.w);
            uint32_t wd = (uint32_t)(half * 64 + 8 * s);
            sts128(aRowH + (((wd    ) ^ sz4) << 2), h0, h1, h2, h3);
            sts128(aRowH + (((wd + 4) ^ sz4) << 2), h4, h5, h6, h7);

            float2 g0 = h22f2(h0), g1 = h22f2(h1), g2 = h22f2(h2), g3 = h22f2(h3);
            float2 g4 = h22f2(h4), g5 = h22f2(h5), g6 = h22f2(h6), g7 = h22f2(h7);
            uint32_t lo0 = (uint32_t)pack_e4m3((f0.x - g0.x) * LO_SCALE, (f0.y - g0.y) * LO_SCALE)
                         | ((uint32_t)pack_e4m3((f0.z - g1.x) * LO_SCALE, (f0.w - g1.y) * LO_SCALE) << 16);
            uint32_t lo1 = (uint32_t)pack_e4m3((f1.x - g2.x) * LO_SCALE, (f1.y - g2.y) * LO_SCALE)
                         | ((uint32_t)pack_e4m3((f1.z - g3.x) * LO_SCALE, (f1.w - g3.y) * LO_SCALE) << 16);
            uint32_t lo2 = (uint32_t)pack_e4m3((f2.x - g4.x) * LO_SCALE, (f2.y - g4.y) * LO_SCALE)
                         | ((uint32_t)pack_e4m3((f2.z - g5.x) * LO_SCALE, (f2.w - g5.y) * LO_SCALE) << 16);
            uint32_t lo3 = (uint32_t)pack_e4m3((f3.x - g6.x) * LO_SCALE, (f3.y - g6.y) * LO_SCALE)
                         | ((uint32_t)pack_e4m3((f3.z - g7.x) * LO_SCALE, (f3.w - g7.y) * LO_SCALE) << 16);
            uint32_t hi0 = (uint32_t)pack_e4m3(f0.x, f0.y) | ((uint32_t)pack_e4m3(f0.z, f0.w) << 16);
            uint32_t hi1 = (uint32_t)pack_e4m3(f1.x, f1.y) | ((uint32_t)pack_e4m3(f1.z, f1.w) << 16);
            uint32_t hi2 = (uint32_t)pack_e4m3(f2.x, f2.y) | ((uint32_t)pack_e4m3(f2.z, f2.w) << 16);
            uint32_t hi3 = (uint32_t)pack_e4m3(f3.x, f3.y) | ((uint32_t)pack_e4m3(f3.z, f3.w) << 16);
            uint32_t wc = (uint32_t)((half * 8 + s) * 8);
            sts128(aRowC + (((wc    ) ^ sz4) << 2), lo0, lo1, lo2, lo3);
            sts128(aRowC + (((wc + 4) ^ sz4) << 2), hi0, hi1, hi2, hi3);
        }
    }
    __syncthreads();

    float accF[2][8][4] = {};
    float accC[2][8][4] = {};
    const float* cs_all = (const float*)(smem + SCS);
    const float* vs_all = (const float*)(smem + SVS);
    float* slog = (float*)(smem + SLOG);

    for (int q = 0; q < 8; q++) {
        if (q < 7) asm volatile("cp.async.wait_group 1;" ::: "memory");
        else       asm volatile("cp.async.wait_group 0;" ::: "memory");
        __syncthreads();

        uint32_t BbufH = S + SBH + (uint32_t)(q & 1) * 16384u;
        uint32_t BbufC = S + SBC + (uint32_t)(q & 1) * 16384u;

#pragma unroll
        for (int ks = 0; ks < 4; ks++) {
            int kg = ((q & 3) << 2) + ks;   // both N-passes traverse same A k-range
            uint32_t offA = (((uint32_t)(2 * kg) + ghalfA) ^ sA) << 4;
            uint32_t ah0[4], ah1[4], ac0[4], ac1[4];
            LDM4(ah0, aBase0  + offA);
            LDM4(ah1, aBase1  + offA);
            LDM4(ac0, aCBase0 + offA);
            LDM4(ac1, aCBase1 + offA);

            uint32_t offB = (((uint32_t)(2 * ks) + ghalfB) ^ sBl) << 4;
            uint32_t bh[4][4], bc[4][4];
            uint32_t bAh = BbufH + bRow0 + offB;
            uint32_t bAc = BbufC + bRow0 + offB;
#pragma unroll
            for (int g = 0; g < 4; g++) {
                LDM4(bh[g], bAh + (uint32_t)g * 2048u);
                LDM4(bc[g], bAc + (uint32_t)g * 2048u);
            }
#pragma unroll
            for (int g = 0; g < 4; g++) {
#pragma unroll
                for (int sub = 0; sub < 2; sub++) {
                    int ni = 2 * g + sub;
                    uint32_t b0h = bh[g][2 * sub], b1h = bh[g][2 * sub + 1];
                    uint32_t b0c = bc[g][2 * sub], b1c = bc[g][2 * sub + 1];
                    mma_f32(accF[0][ni], ah0, b0h, b1h);
                    mma_fp8(accC[0][ni], ac0, b0c, b1c);
                    mma_f32(accF[1][ni], ah1, b0h, b1h);
                    mma_fp8(accC[1][ni], ac1, b0c, b1c);
                }
            }
        }

        // ---- pass epilogue after chunks 3 and 7 ----
        if ((q & 3) == 3) {
            int p = q >> 2;
            const float* cs = cs_all + p * 128;
            const float* vs = vs_all + p * 128;
#pragma unroll
            for (int mi = 0; mi < 2; mi++) {
                float s0 = 0.f, s1 = 0.f;
#pragma unroll
                for (int ni = 0; ni < 8; ni++) {
                    int c0 = nb + ni * 8 + tig * 2;
                    float vv0 = vs[c0], vv1 = vs[c0 + 1];
                    float cc0 = cs[c0], cc1 = cs[c0 + 1];
                    float p0 = (accF[mi][ni][0] + accC[mi][ni][0] * INV_LO_SCALE) * INV_WSCALE + cc0;
                    float p1 = (accF[mi][ni][1] + accC[mi][ni][1] * INV_LO_SCALE) * INV_WSCALE + cc1;
                    float p2 = (accF[mi][ni][2] + accC[mi][ni][2] * INV_LO_SCALE) * INV_WSCALE + cc0;
                    float p3 = (accF[mi][ni][3] + accC[mi][ni][3] * INV_LO_SCALE) * INV_WSCALE + cc1;
                    s0 += vv0 * tanhf(p0) + vv1 * tanhf(p1);
                    s1 += vv0 * tanhf(p2) + vv1 * tanhf(p3);
#pragma unroll
                    for (int j = 0; j < 4; j++) {
                        accF[mi][ni][j] = 0.f;
                        accC[mi][ni][j] = 0.f;
                    }
                }
                s0 += __shfl_xor_sync(0xffffffffu, s0, 1);
                s0 += __shfl_xor_sync(0xffffffffu, s0, 2);
                s1 += __shfl_xor_sync(0xffffffffu, s1, 1);
                s1 += __shfl_xor_sync(0xffffffffu, s1, 2);
                if (tig == 0) {
                    int r0 = mbase + mi * 16 + grp;
                    slog[r0 * 2 + (w >> 2)]       += s0;
                    slog[(r0 + 8) * 2 + (w >> 2)] += s1;
                }
            }
        }

        __syncthreads();
        if (q < 6) {
            issue_b(S, q + 2, t);
            asm volatile("cp.async.commit_group;" ::: "memory");
        }
    }

    // ---- finalize logits, per-tile softmax stats ----
    float* redm = (float*)(smem + SRED);
    float* reds = (float*)(smem + SRED + 16);
    float* es   = (float*)(smem + SES);
    float logit = 0.f;
    if (t < 128) {
        logit = slog[t * 2] + slog[t * 2 + 1];
        attn[rowbase + t] = logit;
        float m = logit;
#pragma unroll
        for (int off = 16; off > 0; off >>= 1)
            m = fmaxf(m, __shfl_xor_sync(0xffffffffu, m, off));
        if (lane == 0) redm[t >> 5] = m;
    }
    __syncthreads();
    float m_tile = fmaxf(fmaxf(redm[0], redm[1]), fmaxf(redm[2], redm[3]));
    if (t < 128) {
        float e = expf(logit - m_tile);
        es[t] = e;
        float se = e;
#pragma unroll
        for (int off = 16; off > 0; off >>= 1)
            se += __shfl_xor_sync(0xffffffffu, se, off);
        if (lane == 0) reds[t >> 5] = se;
    }
    __syncthreads();
    if (t == 0) {
        g_msum[tile * 2]     = m_tile;
        g_msum[tile * 2 + 1] = (reds[0] + reds[1]) + (reds[2] + reds[3]);
    }

    // ---- fused partial context: num[h] = sum_s e_s * enc_hi[s,h] ----
    {
        int wc = t & 127, sh = t >> 7;
        float nx = 0.f, ny = 0.f;
#pragma unroll 4
        for (int s5 = 0; s5 < 64; s5++) {
            int s = sh * 64 + s5;
            uint32_t ws = (uint32_t)s * 128u + ((uint32_t)wc ^ (((uint32_t)s & 7u) << 2));
            float2 f = h22f2(lds32(S + SA_HI + (ws << 2)));
            float e = es[s];
            nx += e * f.x;
            ny += e * f.y;
        }
        float2* comb = (float2*)(smem + SBH);   // B buffers free now
        comb[t] = make_float2(nx, ny);
        __syncthreads();
        if (t < 128) {
            float2 a = comb[t], bb = comb[t + 128];
            float2 r = make_float2(a.x + bb.x, a.y + bb.y);
            ((float2*)(g_pctx + (size_t)tile * HID))[t] = r;
        }
    }
}

// ---------------------------------------------------------------------------
// softmax over S per batch, in place (1024 threads)
// ---------------------------------------------------------------------------
__global__ void softmax_kernel(float* __restrict__ attn) {
    __shared__ float red[1024];
    int b = blockIdx.x;
    int t = threadIdx.x;
    float4* row = (float4*)(attn + (size_t)b * NS);

    float mx = -1e30f;
    for (int i = t; i < NS / 4; i += 1024) {
        float4 x = row[i];
        mx = fmaxf(mx, fmaxf(fmaxf(x.x, x.y), fmaxf(x.z, x.w)));
    }
    red[t] = mx; __syncthreads();
    for (int o = 512; o > 0; o >>= 1) {
        if (t < o) red[t] = fmaxf(red[t], red[t + o]);
        __syncthreads();
    }
    mx = red[0];
    __syncthreads();

    float sum = 0.f;
    for (int i = t; i < NS / 4; i += 1024) {
        float4 x = row[i];
        x.x = expf(x.x - mx); x.y = expf(x.y - mx);
        x.z = expf(x.z - mx); x.w = expf(x.w - mx);
        row[i] = x;
        sum += (x.x + x.y) + (x.z + x.w);
    }
    red[t] = sum; __syncthreads();
    for (int o = 512; o > 0; o >>= 1) {
        if (t < o) red[t] += red[t + o];
        __syncthreads();
    }
    float inv = 1.f / red[0];
    for (int i = t; i < NS / 4; i += 1024) {
        float4 x = row[i];
        x.x *= inv; x.y *= inv; x.z *= inv; x.w *= inv;
        row[i] = x;
    }
}

// ---------------------------------------------------------------------------
// ctx_final: combine per-tile partial contexts with global-max rescale
// ---------------------------------------------------------------------------
__global__ void ctx_final_kernel(float* __restrict__ ctx) {
    __shared__ float sm[64], ss[64], sc[64];
    int b = blockIdx.x;
    int t = threadIdx.x;   // 256
    if (t < 64) {
        sm[t] = g_msum[(b * 64 + t) * 2];
        ss[t] = g_msum[(b * 64 + t) * 2 + 1];
    }
    __syncthreads();
    if (t == 0) {
        float M = sm[0];
#pragma unroll
        for (int i = 1; i < 64; i++) M = fmaxf(M, sm[i]);
        float D = 0.f;
        for (int i = 0; i < 64; i++) {
            float sci = expf(sm[i] - M);
            sc[i] = sci;
            D += sci * ss[i];
        }
        float invD = 1.f / D;
        for (int i = 0; i < 64; i++) sc[i] *= invD;
    }
    __syncthreads();
    float acc = 0.f;
#pragma unroll 8
    for (int i = 0; i < 64; i++)
        acc += sc[i] * g_pctx[(size_t)(b * 64 + i) * HID + t];
    ctx[b * HID + t] = acc;
}

// ---------------------------------------------------------------------------
extern "C" void kernel_launch(void* const* d_in, const int* in_sizes, int n_in,
                              void* d_out, int out_size) {
    const float* hidden = (const float*)d_in[0];  // (1,32,256)
    const float* enc    = (const float*)d_in[1];  // (32,8192,256)
    const float* W      = (const float*)d_in[2];  // (256,512)
    const float* bias   = (const float*)d_in[3];  // (256,)
    const float* v      = (const float*)d_in[4];  // (256,)

    float* out  = (float*)d_out;
    float* ctx  = out;            // (32,256) first
    float* attn = out + NB * HID; // (32,8192) second

    cudaFuncSetAttribute(main_mma_kernel,
                         cudaFuncAttributeMaxDynamicSharedMemorySize, SMEM_MAIN);

    prep_w_kernel<<<128, 256>>>(W);
    compute_c_kernel<<<NB, HID>>>(hidden, W, bias);
    main_mma_kernel<<<2048, 256, SMEM_MAIN>>>(enc, v, attn);
    softmax_kernel<<<NB, 1024>>>(attn);
    ctx_final_kernel<<<NB, 256>>>(ctx);
}

// round 10
// speedup vs baseline: 1.3493x; 1.3493x over previous
#include <cuda_runtime.h>
#include <cuda_fp16.h>
#include <cstdint>

#define HID 256
#define NB 32
#define NS 8192

// SMEM byte offsets (main kernel)
#define SA_HI 0          // A hi plane: 128 rows x 512B (f16) = 64KB
#define SBH   65536      // B f16-hi double buffer: 2 x 16KB
#define SBL   98304      // B f16-lo double buffer: 2 x 16KB
#define SCS   131072     // c[b,*] 1KB
#define SVS   132096     // v 1KB
#define SLOG  133120     // 128 rows x 2 slots floats
#define SES   134144     // 128 exp values
#define SRED  134656     // reduce scratch
#define SMEM_MAIN 135168

#define WSCALE 32.0f
#define INV_WSCALE 0.03125f

__device__ float    g_c[NB * HID];
__device__ uint32_t g_whi[HID * 128];   // 32*We f16-hi, [k_out][h/2] f16x2
__device__ uint32_t g_wlo[HID * 128];   // 32*We f16-lo
__device__ float    g_pctx[2048 * HID]; // per-tile unnormalized context
__device__ float    g_msum[2048 * 2];   // per-tile (max, sum_exp)

// ---------------- helpers ----------------
__device__ __forceinline__ uint32_t cvta_smem(const void* p) {
    uint32_t a;
    asm("{ .reg .u64 t; cvta.to.shared.u64 t, %1; cvt.u32.u64 %0, t; }" : "=r"(a) : "l"(p));
    return a;
}
// pack two floats -> f16x2 (low half = f16(x0), high half = f16(x1))
__device__ __forceinline__ uint32_t pack_f16(float x0, float x1) {
    uint32_t r;
    asm("cvt.rn.f16x2.f32 %0, %1, %2;" : "=r"(r) : "f"(x1), "f"(x0));
    return r;
}
__device__ __forceinline__ float2 h22f2(uint32_t w) {
    __half2 h = *reinterpret_cast<__half2*>(&w);
    return __half22float2(h);
}
__device__ __forceinline__ uint32_t lds32(uint32_t a) {
    uint32_t r;
    asm("ld.shared.b32 %0, [%1];" : "=r"(r) : "r"(a));
    return r;
}
__device__ __forceinline__ void sts128(uint32_t a, uint32_t x, uint32_t y, uint32_t z, uint32_t w) {
    asm volatile("st.shared.v4.b32 [%0], {%1,%2,%3,%4};" :: "r"(a), "r"(x), "r"(y), "r"(z), "r"(w) : "memory");
}
__device__ __forceinline__ void cp_async16(uint32_t saddr, const void* gptr) {
    uint64_t g;
    asm("cvta.to.global.u64 %0, %1;" : "=l"(g) : "l"(gptr));
    asm volatile("cp.async.cg.shared.global [%0], [%1], 16;" :: "r"(saddr), "l"(g) : "memory");
}
// fp16 x fp16, fp32 accumulate
__device__ __forceinline__ void mma_f32(float* c,
        const uint32_t* a, uint32_t b0, uint32_t b1) {
    asm("mma.sync.aligned.m16n8k16.row.col.f32.f16.f16.f32 "
        "{%0,%1,%2,%3}, {%4,%5,%6,%7}, {%8,%9}, {%0,%1,%2,%3};"
        : "+f"(c[0]), "+f"(c[1]), "+f"(c[2]), "+f"(c[3])
        : "r"(a[0]), "r"(a[1]), "r"(a[2]), "r"(a[3]), "r"(b0), "r"(b1));
}
#define LDM4(r, a) \
    asm volatile("ldmatrix.sync.aligned.m8n8.x4.shared.b16 {%0,%1,%2,%3}, [%4];" \
        : "=r"((r)[0]), "=r"((r)[1]), "=r"((r)[2]), "=r"((r)[3]) : "r"(a))

// ---------------------------------------------------------------------------
// prep: 32*We[k,h] -> f16 hi/lo planes (exact-B split: b_hi + b_lo == b to 2^-24)
// ---------------------------------------------------------------------------
__global__ void prep_w_kernel(const float* __restrict__ W) {
    int idx = blockIdx.x * 256 + threadIdx.x;  // 0..32767
    int n = idx >> 7, wp = idx & 127;
    float x0 = WSCALE * W[n * 512 + 256 + wp * 2];
    float x1 = WSCALE * W[n * 512 + 257 + wp * 2];
    uint32_t hi = pack_f16(x0, x1);
    float2 f = h22f2(hi);
    uint32_t lo = pack_f16(x0 - f.x, x1 - f.y);
    g_whi[idx] = hi;
    g_wlo[idx] = lo;
}

// ---------------------------------------------------------------------------
// c[b,k] = bias[k] + sum_h hidden[b,h] * W[k,h]
// ---------------------------------------------------------------------------
__global__ void compute_c_kernel(const float* __restrict__ hidden,
                                 const float* __restrict__ W,
                                 const float* __restrict__ bias) {
    __shared__ float hs[HID];
    int b = blockIdx.x;
    int k = threadIdx.x;
    hs[k] = hidden[b * HID + k];
    __syncthreads();
    float acc = bias[k];
    const float4* wr = (const float4*)(W + (size_t)k * (2 * HID));
#pragma unroll 8
    for (int h4 = 0; h4 < HID / 4; h4++) {
        float4 w = wr[h4];
        acc += w.x * hs[h4 * 4 + 0] + w.y * hs[h4 * 4 + 1]
             + w.z * hs[h4 * 4 + 2] + w.w * hs[h4 * 4 + 3];
    }
    g_c[b * HID + k] = acc;
}

// ---------------------------------------------------------------------------
// stream B chunk q (f16-hi 16KB + f16-lo 16KB) into buf q&1
// ---------------------------------------------------------------------------
__device__ __forceinline__ void issue_b(uint32_t S, int q, int t) {
    int p = q >> 2, cc = q & 3;
    uint32_t bufH = S + SBH + (uint32_t)(q & 1) * 16384u;
    uint32_t bufL = S + SBL + (uint32_t)(q & 1) * 16384u;
    int n  = t >> 1;
    int wq = (t & 1) * 16;
    const uint32_t* srcH = g_whi + (size_t)(p * 128 + n) * 128 + cc * 32 + wq;
    const uint32_t* srcL = g_wlo + (size_t)(p * 128 + n) * 128 + cc * 32 + wq;
    uint32_t sz   = ((uint32_t)n & 7) << 2;
    uint32_t wrow = (uint32_t)n * 32;
#pragma unroll
    for (int j = 0; j < 4; j++) {
        uint32_t wc = (uint32_t)(wq + j * 4);
        uint32_t ad = (wrow + (wc ^ sz)) << 2;
        cp_async16(bufH + ad, srcH + j * 4);
        cp_async16(bufL + ad, srcL + j * 4);
    }
}

// ---------------------------------------------------------------------------
// Main fused kernel: logits + fused partial softmax-context.
// 2-term exact-B split: pre = a_hi*(b_hi + b_lo), both MMAs fp32-acc same dest.
// ---------------------------------------------------------------------------
__global__ void __launch_bounds__(256, 1) main_mma_kernel(
    const float* __restrict__ enc, const float* __restrict__ v,
    float* __restrict__ attn)
{
    extern __shared__ char smem[];
    const uint32_t S = cvta_smem(smem);

    int t = threadIdx.x;
    int lane = t & 31, w = t >> 5;
    int grp = lane >> 2, tig = lane & 3;
    int mbase = (w & 3) * 32;
    int nb    = (w >> 2) * 64;

    int tile  = blockIdx.x;          // 0..2047
    int b     = tile >> 6;
    int tm    = (tile & 63) * 128;
    size_t rowbase = (size_t)b * NS + tm;

    // ldmatrix lane addressing
    int lrow   = lane & 15;
    uint32_t ghalfA = (uint32_t)(lane >> 4);
    uint32_t sA     = (uint32_t)(lrow & 7);
    uint32_t aBase0 = S + SA_HI + (uint32_t)(mbase + lrow) * 512u;
    uint32_t aBase1 = aBase0 + 16u * 512u;
    uint32_t ghalfB = (uint32_t)((lane >> 3) & 1);
    uint32_t sBl    = (uint32_t)(lane & 7);
    uint32_t bRow0  = ((uint32_t)(nb + (lane & 7) + ((lane >> 4) & 1) * 8)) * 128u;

    ((float*)(smem + SCS))[t] = g_c[b * HID + t];
    ((float*)(smem + SVS))[t] = v[t];
    ((float*)(smem + SLOG))[t] = 0.f;

    issue_b(S, 0, t);
    asm volatile("cp.async.commit_group;" ::: "memory");
    issue_b(S, 1, t);
    asm volatile("cp.async.commit_group;" ::: "memory");

    // ---- A load: f16-hi plane only ----
    {
        int row = t >> 1, half = t & 1;
        const float4* src = ((const float4*)(enc + (rowbase + (size_t)row) * HID)) + half * 32;
        uint32_t wbase = (uint32_t)row * 128 + (uint32_t)half * 64;
        uint32_t sz = ((uint32_t)row & 7) << 2;
#pragma unroll 4
        for (int j = 0; j < 16; j++) {
            float4 f0 = src[2 * j], f1 = src[2 * j + 1];
            uint32_t h0 = pack_f16(f0.x, f0.y);
            uint32_t h1 = pack_f16(f0.z, f0.w);
            uint32_t h2 = pack_f16(f1.x, f1.y);
            uint32_t h3 = pack_f16(f1.z, f1.w);
            uint32_t wd = wbase + (uint32_t)j * 4;
            sts128(S + SA_HI + ((wd ^ sz) << 2), h0, h1, h2, h3);
        }
    }
    __syncthreads();

    float accF[2][8][4] = {};
    const float* cs_all = (const float*)(smem + SCS);
    const float* vs_all = (const float*)(smem + SVS);
    float* slog = (float*)(smem + SLOG);

    for (int q = 0; q < 8; q++) {
        if (q < 7) asm volatile("cp.async.wait_group 1;" ::: "memory");
        else       asm volatile("cp.async.wait_group 0;" ::: "memory");
        __syncthreads();

        uint32_t BbufH = S + SBH + (uint32_t)(q & 1) * 16384u;
        uint32_t BbufL = S + SBL + (uint32_t)(q & 1) * 16384u;

#pragma unroll
        for (int ks = 0; ks < 4; ks++) {
            int kg = ((q & 3) << 2) + ks;   // both N-passes traverse same A k-range
            uint32_t offA = (((uint32_t)(2 * kg) + ghalfA) ^ sA) << 4;
            uint32_t ah0[4], ah1[4];
            LDM4(ah0, aBase0 + offA);
            LDM4(ah1, aBase1 + offA);

            uint32_t offB = (((uint32_t)(2 * ks) + ghalfB) ^ sBl) << 4;
            uint32_t bh[4][4], bl[4][4];
            uint32_t bAh = BbufH + bRow0 + offB;
            uint32_t bAl = BbufL + bRow0 + offB;
#pragma unroll
            for (int g = 0; g < 4; g++) {
                LDM4(bh[g], bAh + (uint32_t)g * 2048u);
                LDM4(bl[g], bAl + (uint32_t)g * 2048u);
            }
#pragma unroll
            for (int g = 0; g < 4; g++) {
#pragma unroll
                for (int sub = 0; sub < 2; sub++) {
                    int ni = 2 * g + sub;
                    uint32_t b0h = bh[g][2 * sub], b1h = bh[g][2 * sub + 1];
                    uint32_t b0l = bl[g][2 * sub], b1l = bl[g][2 * sub + 1];
                    mma_f32(accF[0][ni], ah0, b0h, b1h);
                    mma_f32(accF[0][ni], ah0, b0l, b1l);
                    mma_f32(accF[1][ni], ah1, b0h, b1h);
                    mma_f32(accF[1][ni], ah1, b0l, b1l);
                }
            }
        }

        // ---- pass epilogue after chunks 3 and 7 ----
        if ((q & 3) == 3) {
            int p = q >> 2;
            const float* cs = cs_all + p * 128;
            const float* vs = vs_all + p * 128;
#pragma unroll
            for (int mi = 0; mi < 2; mi++) {
                float s0 = 0.f, s1 = 0.f;
#pragma unroll
                for (int ni = 0; ni < 8; ni++) {
                    int c0 = nb + ni * 8 + tig * 2;
                    float vv0 = vs[c0], vv1 = vs[c0 + 1];
                    float cc0 = cs[c0], cc1 = cs[c0 + 1];
                    float p0 = accF[mi][ni][0] * INV_WSCALE + cc0;
                    float p1 = accF[mi][ni][1] * INV_WSCALE + cc1;
                    float p2 = accF[mi][ni][2] * INV_WSCALE + cc0;
                    float p3 = accF[mi][ni][3] * INV_WSCALE + cc1;
                    s0 += vv0 * tanhf(p0) + vv1 * tanhf(p1);
                    s1 += vv0 * tanhf(p2) + vv1 * tanhf(p3);
#pragma unroll
                    for (int j = 0; j < 4; j++) accF[mi][ni][j] = 0.f;
                }
                s0 += __shfl_xor_sync(0xffffffffu, s0, 1);
                s0 += __shfl_xor_sync(0xffffffffu, s0, 2);
                s1 += __shfl_xor_sync(0xffffffffu, s1, 1);
                s1 += __shfl_xor_sync(0xffffffffu, s1, 2);
                if (tig == 0) {
                    int r0 = mbase + mi * 16 + grp;
                    slog[r0 * 2 + (w >> 2)]       += s0;
                    slog[(r0 + 8) * 2 + (w >> 2)] += s1;
                }
            }
        }

        __syncthreads();
        if (q < 6) {
            issue_b(S, q + 2, t);
            asm volatile("cp.async.commit_group;" ::: "memory");
        }
    }

    // ---- finalize logits, per-tile softmax stats ----
    float* redm = (float*)(smem + SRED);
    float* reds = (float*)(smem + SRED + 16);
    float* es   = (float*)(smem + SES);
    float logit = 0.f;
    if (t < 128) {
        logit = slog[t * 2] + slog[t * 2 + 1];
        attn[rowbase + t] = logit;
        float m = logit;
#pragma unroll
        for (int off = 16; off > 0; off >>= 1)
            m = fmaxf(m, __shfl_xor_sync(0xffffffffu, m, off));
        if (lane == 0) redm[t >> 5] = m;
    }
    __syncthreads();
    float m_tile = fmaxf(fmaxf(redm[0], redm[1]), fmaxf(redm[2], redm[3]));
    if (t < 128) {
        float e = expf(logit - m_tile);
        es[t] = e;
        float se = e;
#pragma unroll
        for (int off = 16; off > 0; off >>= 1)
            se += __shfl_xor_sync(0xffffffffu, se, off);
        if (lane == 0) reds[t >> 5] = se;
    }
    __syncthreads();
    if (t == 0) {
        g_msum[tile * 2]     = m_tile;
        g_msum[tile * 2 + 1] = (reds[0] + reds[1]) + (reds[2] + reds[3]);
    }

    // ---- fused partial context: num[h] = sum_s e_s * enc_hi[s,h] ----
    {
        int wc = t & 127, sh = t >> 7;
        float nx = 0.f, ny = 0.f;
#pragma unroll 4
        for (int s5 = 0; s5 < 64; s5++) {
            int s = sh * 64 + s5;
            uint32_t ws = (uint32_t)s * 128u + ((uint32_t)wc ^ (((uint32_t)s & 7u) << 2));
            float2 f = h22f2(lds32(S + SA_HI + (ws << 2)));
            float e = es[s];
            nx += e * f.x;
            ny += e * f.y;
        }
        float2* comb = (float2*)(smem + SBH);   // B buffers free now
        comb[t] = make_float2(nx, ny);
        __syncthreads();
        if (t < 128) {
            float2 a = comb[t], bb = comb[t + 128];
            float2 r = make_float2(a.x + bb.x, a.y + bb.y);
            ((float2*)(g_pctx + (size_t)tile * HID))[t] = r;
        }
    }
}

// ---------------------------------------------------------------------------
// softmax over S per batch, in place (1024 threads)
// ---------------------------------------------------------------------------
__global__ void softmax_kernel(float* __restrict__ attn) {
    __shared__ float red[1024];
    int b = blockIdx.x;
    int t = threadIdx.x;
    float4* row = (float4*)(attn + (size_t)b * NS);

    float mx = -1e30f;
    for (int i = t; i < NS / 4; i += 1024) {
        float4 x = row[i];
        mx = fmaxf(mx, fmaxf(fmaxf(x.x, x.y), fmaxf(x.z, x.w)));
    }
    red[t] = mx; __syncthreads();
    for (int o = 512; o > 0; o >>= 1) {
        if (t < o) red[t] = fmaxf(red[t], red[t + o]);
        __syncthreads();
    }
    mx = red[0];
    __syncthreads();

    float sum = 0.f;
    for (int i = t; i < NS / 4; i += 1024) {
        float4 x = row[i];
        x.x = expf(x.x - mx); x.y = expf(x.y - mx);
        x.z = expf(x.z - mx); x.w = expf(x.w - mx);
        row[i] = x;
        sum += (x.x + x.y) + (x.z + x.w);
    }
    red[t] = sum; __syncthreads();
    for (int o = 512; o > 0; o >>= 1) {
        if (t < o) red[t] += red[t + o];
        __syncthreads();
    }
    float inv = 1.f / red[0];
    for (int i = t; i < NS / 4; i += 1024) {
        float4 x = row[i];
        x.x *= inv; x.y *= inv; x.z *= inv; x.w *= inv;
        row[i] = x;
    }
}

// ---------------------------------------------------------------------------
// ctx_final: combine per-tile partial contexts with global-max rescale
// ---------------------------------------------------------------------------
__global__ void ctx_final_kernel(float* __restrict__ ctx) {
    __shared__ float sm[64], ss[64], sc[64];
    int b = blockIdx.x;
    int t = threadIdx.x;   // 256
    if (t < 64) {
        sm[t] = g_msum[(b * 64 + t) * 2];
        ss[t] = g_msum[(b * 64 + t) * 2 + 1];
    }
    __syncthreads();
    if (t == 0) {
        float M = sm[0];
#pragma unroll
        for (int i = 1; i < 64; i++) M = fmaxf(M, sm[i]);
        float D = 0.f;
        for (int i = 0; i < 64; i++) {
            float sci = expf(sm[i] - M);
            sc[i] = sci;
            D += sci * ss[i];
        }
        float invD = 1.f / D;
        for (int i = 0; i < 64; i++) sc[i] *= invD;
    }
    __syncthreads();
    float acc = 0.f;
#pragma unroll 8
    for (int i = 0; i < 64; i++)
        acc += sc[i] * g_pctx[(size_t)(b * 64 + i) * HID + t];
    ctx[b * HID + t] = acc;
}

// ---------------------------------------------------------------------------
extern "C" void kernel_launch(void* const* d_in, const int* in_sizes, int n_in,
                              void* d_out, int out_size) {
    const float* hidden = (const float*)d_in[0];  // (1,32,256)
    const float* enc    = (const float*)d_in[1];  // (32,8192,256)
    const float* W      = (const float*)d_in[2];  // (256,512)
    const float* bias   = (const float*)d_in[3];  // (256,)
    const float* v      = (const float*)d_in[4];  // (256,)

    float* out  = (float*)d_out;
    float* ctx  = out;            // (32,256) first
    float* attn = out + NB * HID; // (32,8192) second

    cudaFuncSetAttribute(main_mma_kernel,
                         cudaFuncAttributeMaxDynamicSharedMemorySize, SMEM_MAIN);

    prep_w_kernel<<<128, 256>>>(W);
    compute_c_kernel<<<NB, HID>>>(hidden, W, bias);
    main_mma_kernel<<<2048, 256, SMEM_MAIN>>>(enc, v, attn);
    softmax_kernel<<<NB, 1024>>>(attn);
    ctx_final_kernel<<<NB, 256>>>(ctx);
}

// round 11
// speedup vs baseline: 1.8026x; 1.3360x over previous
#include <cuda_runtime.h>
#include <cuda_fp16.h>
#include <cstdint>

#define HID 256
#define NB 32
#define NS 8192

// SMEM byte offsets (main kernel)
#define SA_HI 0          // A plane: 128 rows x 512B (f16) = 64KB
#define SB    65536      // B resident: 8 chunks x 16KB = 128KB
#define SCS   196608     // c[b,*] 1KB
#define SVS   197632     // v 1KB
#define SLOG  198656     // 128 rows x 2 slots floats
#define SES   199680     // 128 exp values
#define SRED  200192     // reduce scratch
#define SMEM_MAIN 200704

__device__ float    g_c[NB * HID];
__device__ uint32_t g_whi[HID * 128];   // We f16, [k_out][h/2] f16x2
__device__ float    g_pctx[2048 * HID]; // per-tile unnormalized context
__device__ float    g_msum[2048 * 2];   // per-tile (max, sum_exp)

// ---------------- helpers ----------------
__device__ __forceinline__ uint32_t cvta_smem(const void* p) {
    uint32_t a;
    asm("{ .reg .u64 t; cvta.to.shared.u64 t, %1; cvt.u32.u64 %0, t; }" : "=r"(a) : "l"(p));
    return a;
}
// pack two floats -> f16x2 (low half = f16(x0), high half = f16(x1))
__device__ __forceinline__ uint32_t pack_f16(float x0, float x1) {
    uint32_t r;
    asm("cvt.rn.f16x2.f32 %0, %1, %2;" : "=r"(r) : "f"(x1), "f"(x0));
    return r;
}
__device__ __forceinline__ float2 h22f2(uint32_t w) {
    __half2 h = *reinterpret_cast<__half2*>(&w);
    return __half22float2(h);
}
__device__ __forceinline__ uint32_t lds32(uint32_t a) {
    uint32_t r;
    asm("ld.shared.b32 %0, [%1];" : "=r"(r) : "r"(a));
    return r;
}
__device__ __forceinline__ void sts128(uint32_t a, uint32_t x, uint32_t y, uint32_t z, uint32_t w) {
    asm volatile("st.shared.v4.b32 [%0], {%1,%2,%3,%4};" :: "r"(a), "r"(x), "r"(y), "r"(z), "r"(w) : "memory");
}
__device__ __forceinline__ void cp_async16(uint32_t saddr, const void* gptr) {
    uint64_t g;
    asm("cvta.to.global.u64 %0, %1;" : "=l"(g) : "l"(gptr));
    asm volatile("cp.async.cg.shared.global [%0], [%1], 16;" :: "r"(saddr), "l"(g) : "memory");
}
// fp16 x fp16, fp32 accumulate
__device__ __forceinline__ void mma_f32(float* c,
        const uint32_t* a, uint32_t b0, uint32_t b1) {
    asm("mma.sync.aligned.m16n8k16.row.col.f32.f16.f16.f32 "
        "{%0,%1,%2,%3}, {%4,%5,%6,%7}, {%8,%9}, {%0,%1,%2,%3};"
        : "+f"(c[0]), "+f"(c[1]), "+f"(c[2]), "+f"(c[3])
        : "r"(a[0]), "r"(a[1]), "r"(a[2]), "r"(a[3]), "r"(b0), "r"(b1));
}
#define LDM4(r, a) \
    asm volatile("ldmatrix.sync.aligned.m8n8.x4.shared.b16 {%0,%1,%2,%3}, [%4];" \
        : "=r"((r)[0]), "=r"((r)[1]), "=r"((r)[2]), "=r"((r)[3]) : "r"(a))

// ---------------------------------------------------------------------------
// prep: We[k,h] = W[k, 256+h] -> single f16 plane, [k][h/2] f16x2
// ---------------------------------------------------------------------------
__global__ void prep_w_kernel(const float* __restrict__ W) {
    int idx = blockIdx.x * 256 + threadIdx.x;  // 0..32767
    int n = idx >> 7, wp = idx & 127;
    float x0 = W[n * 512 + 256 + wp * 2];
    float x1 = W[n * 512 + 257 + wp * 2];
    g_whi[idx] = pack_f16(x0, x1);
}

// ---------------------------------------------------------------------------
// c[b,k] = bias[k] + sum_h hidden[b,h] * W[k,h]
// ---------------------------------------------------------------------------
__global__ void compute_c_kernel(const float* __restrict__ hidden,
                                 const float* __restrict__ W,
                                 const float* __restrict__ bias) {
    __shared__ float hs[HID];
    int b = blockIdx.x;
    int k = threadIdx.x;
    hs[k] = hidden[b * HID + k];
    __syncthreads();
    float acc = bias[k];
    const float4* wr = (const float4*)(W + (size_t)k * (2 * HID));
#pragma unroll 8
    for (int h4 = 0; h4 < HID / 4; h4++) {
        float4 w = wr[h4];
        acc += w.x * hs[h4 * 4 + 0] + w.y * hs[h4 * 4 + 1]
             + w.z * hs[h4 * 4 + 2] + w.w * hs[h4 * 4 + 3];
    }
    g_c[b * HID + k] = acc;
}

// ---------------------------------------------------------------------------
// Main fused kernel: logits = v . tanh(enc@We^T + c) + fused partial
// softmax-context. Pure fp16 MMA, fp32 accum. B fully resident in SMEM,
// prefetched once; MMA mainloop has no barriers.
// ---------------------------------------------------------------------------
__global__ void __launch_bounds__(256, 1) main_mma_kernel(
    const float* __restrict__ enc, const float* __restrict__ v,
    float* __restrict__ attn)
{
    extern __shared__ char smem[];
    const uint32_t S = cvta_smem(smem);

    int t = threadIdx.x;
    int lane = t & 31, w = t >> 5;
    int grp = lane >> 2, tig = lane & 3;
    int mbase = (w & 3) * 32;
    int nb    = (w >> 2) * 64;

    int tile  = blockIdx.x;          // 0..2047
    int b     = tile >> 6;
    int tm    = (tile & 63) * 128;
    size_t rowbase = (size_t)b * NS + tm;

    // ldmatrix lane addressing
    int lrow   = lane & 15;
    uint32_t ghalfA = (uint32_t)(lane >> 4);
    uint32_t sA     = (uint32_t)(lrow & 7);
    uint32_t aBase0 = S + SA_HI + (uint32_t)(mbase + lrow) * 512u;
    uint32_t aBase1 = aBase0 + 16u * 512u;
    uint32_t ghalfB = (uint32_t)((lane >> 3) & 1);
    uint32_t sBl    = (uint32_t)(lane & 7);
    uint32_t bRow0  = ((uint32_t)(nb + (lane & 7) + ((lane >> 4) & 1) * 8)) * 128u;

    ((float*)(smem + SCS))[t] = g_c[b * HID + t];
    ((float*)(smem + SVS))[t] = v[t];
    ((float*)(smem + SLOG))[t] = 0.f;

    // ---- prefetch ALL of B (8 chunks x 16KB) in one cp.async group ----
    {
        int n  = t >> 1;                 // 0..127 (k-col within pass)
        int wq = (t & 1) * 16;
        uint32_t sz   = ((uint32_t)n & 7) << 2;
        uint32_t wrow = (uint32_t)n * 32;
#pragma unroll
        for (int q = 0; q < 8; q++) {
            int p = q >> 2, cc = q & 3;
            uint32_t buf = S + SB + (uint32_t)q * 16384u;
            const uint32_t* src = g_whi + (size_t)(p * 128 + n) * 128 + cc * 32 + wq;
#pragma unroll
            for (int j = 0; j < 4; j++) {
                uint32_t wc = (uint32_t)(wq + j * 4);
                cp_async16(buf + ((wrow + (wc ^ sz)) << 2), src + j * 4);
            }
        }
        asm volatile("cp.async.commit_group;" ::: "memory");
    }

    // ---- A load: fp32 -> f16, swizzled STS (overlaps with B prefetch) ----
    {
        int row = t >> 1, half = t & 1;
        const float4* src = ((const float4*)(enc + (rowbase + (size_t)row) * HID)) + half * 32;
        uint32_t wbase = (uint32_t)row * 128 + (uint32_t)half * 64;
        uint32_t sz = ((uint32_t)row & 7) << 2;
#pragma unroll 4
        for (int j = 0; j < 16; j++) {
            float4 f0 = src[2 * j], f1 = src[2 * j + 1];
            uint32_t h0 = pack_f16(f0.x, f0.y);
            uint32_t h1 = pack_f16(f0.z, f0.w);
            uint32_t h2 = pack_f16(f1.x, f1.y);
            uint32_t h3 = pack_f16(f1.z, f1.w);
            uint32_t wd = wbase + (uint32_t)j * 4;
            sts128(S + SA_HI + ((wd ^ sz) << 2), h0, h1, h2, h3);
        }
    }
    asm volatile("cp.async.wait_group 0;" ::: "memory");
    __syncthreads();

    float accF[2][8][4] = {};
    const float* cs_all = (const float*)(smem + SCS);
    const float* vs_all = (const float*)(smem + SVS);
    float* slog = (float*)(smem + SLOG);

    // ---- barrier-free MMA mainloop: 2 passes x 16 ksteps ----
#pragma unroll 1
    for (int p = 0; p < 2; p++) {
#pragma unroll 1
        for (int cc = 0; cc < 4; cc++) {
            uint32_t Bbuf = S + SB + (uint32_t)(p * 4 + cc) * 16384u;
#pragma unroll
            for (int ks = 0; ks < 4; ks++) {
                int kg = (cc << 2) + ks;
                uint32_t offA = (((uint32_t)(2 * kg) + ghalfA) ^ sA) << 4;
                uint32_t ah0[4], ah1[4];
                LDM4(ah0, aBase0 + offA);
                LDM4(ah1, aBase1 + offA);

                uint32_t offB = (((uint32_t)(2 * ks) + ghalfB) ^ sBl) << 4;
                uint32_t bh[4][4];
                uint32_t bAh = Bbuf + bRow0 + offB;
#pragma unroll
                for (int g = 0; g < 4; g++)
                    LDM4(bh[g], bAh + (uint32_t)g * 2048u);
#pragma unroll
                for (int g = 0; g < 4; g++) {
#pragma unroll
                    for (int sub = 0; sub < 2; sub++) {
                        int ni = 2 * g + sub;
                        mma_f32(accF[0][ni], ah0, bh[g][2 * sub], bh[g][2 * sub + 1]);
                        mma_f32(accF[1][ni], ah1, bh[g][2 * sub], bh[g][2 * sub + 1]);
                    }
                }
            }
        }

        // ---- pass epilogue ----
        {
            const float* cs = cs_all + p * 128;
            const float* vs = vs_all + p * 128;
#pragma unroll
            for (int mi = 0; mi < 2; mi++) {
                float s0 = 0.f, s1 = 0.f;
#pragma unroll
                for (int ni = 0; ni < 8; ni++) {
                    int c0 = nb + ni * 8 + tig * 2;
                    float vv0 = vs[c0], vv1 = vs[c0 + 1];
                    float cc0 = cs[c0], cc1 = cs[c0 + 1];
                    s0 += vv0 * tanhf(accF[mi][ni][0] + cc0)
                        + vv1 * tanhf(accF[mi][ni][1] + cc1);
                    s1 += vv0 * tanhf(accF[mi][ni][2] + cc0)
                        + vv1 * tanhf(accF[mi][ni][3] + cc1);
#pragma unroll
                    for (int j = 0; j < 4; j++) accF[mi][ni][j] = 0.f;
                }
                s0 += __shfl_xor_sync(0xffffffffu, s0, 1);
                s0 += __shfl_xor_sync(0xffffffffu, s0, 2);
                s1 += __shfl_xor_sync(0xffffffffu, s1, 1);
                s1 += __shfl_xor_sync(0xffffffffu, s1, 2);
                if (tig == 0) {
                    int r0 = mbase + mi * 16 + grp;
                    slog[r0 * 2 + (w >> 2)]       += s0;
                    slog[(r0 + 8) * 2 + (w >> 2)] += s1;
                }
            }
        }
    }
    __syncthreads();

    // ---- finalize logits, per-tile softmax stats ----
    float* redm = (float*)(smem + SRED);
    float* reds = (float*)(smem + SRED + 16);
    float* es   = (float*)(smem + SES);
    float logit = 0.f;
    if (t < 128) {
        logit = slog[t * 2] + slog[t * 2 + 1];
        attn[rowbase + t] = logit;
        float m = logit;
#pragma unroll
        for (int off = 16; off > 0; off >>= 1)
            m = fmaxf(m, __shfl_xor_sync(0xffffffffu, m, off));
        if (lane == 0) redm[t >> 5] = m;
    }
    __syncthreads();
    float m_tile = fmaxf(fmaxf(redm[0], redm[1]), fmaxf(redm[2], redm[3]));
    if (t < 128) {
        float e = expf(logit - m_tile);
        es[t] = e;
        float se = e;
#pragma unroll
        for (int off = 16; off > 0; off >>= 1)
            se += __shfl_xor_sync(0xffffffffu, se, off);
        if (lane == 0) reds[t >> 5] = se;
    }
    __syncthreads();
    if (t == 0) {
        g_msum[tile * 2]     = m_tile;
        g_msum[tile * 2 + 1] = (reds[0] + reds[1]) + (reds[2] + reds[3]);
    }

    // ---- fused partial context: num[h] = sum_s e_s * enc_f16[s,h] ----
    {
        int wc = t & 127, sh = t >> 7;
        float nx = 0.f, ny = 0.f;
#pragma unroll 4
        for (int s5 = 0; s5 < 64; s5++) {
            int s = sh * 64 + s5;
            uint32_t ws = (uint32_t)s * 128u + ((uint32_t)wc ^ (((uint32_t)s & 7u) << 2));
            float2 f = h22f2(lds32(S + SA_HI + (ws << 2)));
            float e = es[s];
            nx += e * f.x;
            ny += e * f.y;
        }
        float2* comb = (float2*)(smem + SB);   // B region free now
        comb[t] = make_float2(nx, ny);
        __syncthreads();
        if (t < 128) {
            float2 a = comb[t], bb = comb[t + 128];
            float2 r = make_float2(a.x + bb.x, a.y + bb.y);
            ((float2*)(g_pctx + (size_t)tile * HID))[t] = r;
        }
    }
}

// ---------------------------------------------------------------------------
// softmax over S per batch, in place (1024 threads)
// ---------------------------------------------------------------------------
__global__ void softmax_kernel(float* __restrict__ attn) {
    __shared__ float red[1024];
    int b = blockIdx.x;
    int t = threadIdx.x;
    float4* row = (float4*)(attn + (size_t)b * NS);

    float mx = -1e30f;
    for (int i = t; i < NS / 4; i += 1024) {
        float4 x = row[i];
        mx = fmaxf(mx, fmaxf(fmaxf(x.x, x.y), fmaxf(x.z, x.w)));
    }
    red[t] = mx; __syncthreads();
    for (int o = 512; o > 0; o >>= 1) {
        if (t < o) red[t] = fmaxf(red[t], red[t + o]);
        __syncthreads();
    }
    mx = red[0];
    __syncthreads();

    float sum = 0.f;
    for (int i = t; i < NS / 4; i += 1024) {
        float4 x = row[i];
        x.x = expf(x.x - mx); x.y = expf(x.y - mx);
        x.z = expf(x.z - mx); x.w = expf(x.w - mx);
        row[i] = x;
        sum += (x.x + x.y) + (x.z + x.w);
    }
    red[t] = sum; __syncthreads();
    for (int o = 512; o > 0; o >>= 1) {
        if (t < o) red[t] += red[t + o];
        __syncthreads();
    }
    float inv = 1.f / red[0];
    for (int i = t; i < NS / 4; i += 1024) {
        float4 x = row[i];
        x.x *= inv; x.y *= inv; x.z *= inv; x.w *= inv;
        row[i] = x;
    }
}

// ---------------------------------------------------------------------------
// ctx_final: combine per-tile partial contexts with global-max rescale
// ---------------------------------------------------------------------------
__global__ void ctx_final_kernel(float* __restrict__ ctx) {
    __shared__ float sm[64], ss[64], sc[64];
    int b = blockIdx.x;
    int t = threadIdx.x;   // 256
    if (t < 64) {
        sm[t] = g_msum[(b * 64 + t) * 2];
        ss[t] = g_msum[(b * 64 + t) * 2 + 1];
    }
    __syncthreads();
    if (t == 0) {
        float M = sm[0];
#pragma unroll
        for (int i = 1; i < 64; i++) M = fmaxf(M, sm[i]);
        float D = 0.f;
        for (int i = 0; i < 64; i++) {
            float sci = expf(sm[i] - M);
            sc[i] = sci;
            D += sci * ss[i];
        }
        float invD = 1.f / D;
        for (int i = 0; i < 64; i++) sc[i] *= invD;
    }
    __syncthreads();
    float acc = 0.f;
#pragma unroll 8
    for (int i = 0; i < 64; i++)
        acc += sc[i] * g_pctx[(size_t)(b * 64 + i) * HID + t];
    ctx[b * HID + t] = acc;
}

// ---------------------------------------------------------------------------
extern "C" void kernel_launch(void* const* d_in, const int* in_sizes, int n_in,
                              void* d_out, int out_size) {
    const float* hidden = (const float*)d_in[0];  // (1,32,256)
    const float* enc    = (const float*)d_in[1];  // (32,8192,256)
    const float* W      = (const float*)d_in[2];  // (256,512)
    const float* bias   = (const float*)d_in[3];  // (256,)
    const float* v      = (const float*)d_in[4];  // (256,)

    float* out  = (float*)d_out;
    float* ctx  = out;            // (32,256) first
    float* attn = out + NB * HID; // (32,8192) second

    cudaFuncSetAttribute(main_mma_kernel,
                         cudaFuncAttributeMaxDynamicSharedMemorySize, SMEM_MAIN);

    prep_w_kernel<<<128, 256>>>(W);
    compute_c_kernel<<<NB, HID>>>(hidden, W, bias);
    main_mma_kernel<<<2048, 256, SMEM_MAIN>>>(enc, v, attn);
    softmax_kernel<<<NB, 1024>>>(attn);
    ctx_final_kernel<<<NB, 256>>>(ctx);
}

// round 14
// speedup vs baseline: 1.9014x; 1.0548x over previous
#include <cuda_runtime.h>
#include <cuda_fp16.h>
#include <cstdint>

#define HID 256
#define NB 32
#define NS 8192
#define NTILES 2048
#define GRID_MAIN 148

// SMEM byte offsets (main kernel)
#define SA_HI 0          // A plane: 128 rows x 512B (f16) = 64KB
#define SB    65536      // B resident: 8 chunks x 16KB = 128KB (persistent)
#define SCS   196608     // c[b,*] 1KB
#define SVS   197632     // v 1KB
#define SLOG  198656     // 128 rows x 2 slots floats
#define SES   199680     // 128 exp values
#define SRED  200192     // reduce scratch
#define SCOMB 200704     // ctx combine scratch: 256 float2 = 2KB
#define SMEM_MAIN 202752

__device__ float    g_c[NB * HID];
__device__ uint32_t g_whi[HID * 128];     // We f16, [k_out][h/2] f16x2
__device__ float    g_pctx[NTILES * HID]; // per-tile unnormalized context
__device__ float    g_msum[NTILES * 2];   // per-tile (max, sum_exp)

// ---------------- helpers ----------------
__device__ __forceinline__ uint32_t cvta_smem(const void* p) {
    uint32_t a;
    asm("{ .reg .u64 t; cvta.to.shared.u64 t, %1; cvt.u32.u64 %0, t; }" : "=r"(a) : "l"(p));
    return a;
}
__device__ __forceinline__ uint32_t pack_f16(float x0, float x1) {
    uint32_t r;
    asm("cvt.rn.f16x2.f32 %0, %1, %2;" : "=r"(r) : "f"(x1), "f"(x0));
    return r;
}
__device__ __forceinline__ float2 h22f2(uint32_t w) {
    __half2 h = *reinterpret_cast<__half2*>(&w);
    return __half22float2(h);
}
__device__ __forceinline__ uint32_t lds32(uint32_t a) {
    uint32_t r;
    asm("ld.shared.b32 %0, [%1];" : "=r"(r) : "r"(a));
    return r;
}
__device__ __forceinline__ void sts128(uint32_t a, uint32_t x, uint32_t y, uint32_t z, uint32_t w) {
    asm volatile("st.shared.v4.b32 [%0], {%1,%2,%3,%4};" :: "r"(a), "r"(x), "r"(y), "r"(z), "r"(w) : "memory");
}
__device__ __forceinline__ void cp_async16(uint32_t saddr, const void* gptr) {
    uint64_t g;
    asm("cvta.to.global.u64 %0, %1;" : "=l"(g) : "l"(gptr));
    asm volatile("cp.async.cg.shared.global [%0], [%1], 16;" :: "r"(saddr), "l"(g) : "memory");
}
// fp16 x fp16, fp32 accumulate
__device__ __forceinline__ void mma_f32(float* c,
        const uint32_t* a, uint32_t b0, uint32_t b1) {
    asm("mma.sync.aligned.m16n8k16.row.col.f32.f16.f16.f32 "
        "{%0,%1,%2,%3}, {%4,%5,%6,%7}, {%8,%9}, {%0,%1,%2,%3};"
        : "+f"(c[0]), "+f"(c[1]), "+f"(c[2]), "+f"(c[3])
        : "r"(a[0]), "r"(a[1]), "r"(a[2]), "r"(a[3]), "r"(b0), "r"(b1));
}
#define LDM4(r, a) \
    asm volatile("ldmatrix.sync.aligned.m8n8.x4.shared.b16 {%0,%1,%2,%3}, [%4];" \
        : "=r"((r)[0]), "=r"((r)[1]), "=r"((r)[2]), "=r"((r)[3]) : "r"(a))

// ---------------------------------------------------------------------------
// prep: We[k,h] = W[k, 256+h] -> single f16 plane, [k][h/2] f16x2
// ---------------------------------------------------------------------------
__global__ void prep_w_kernel(const float* __restrict__ W) {
    int idx = blockIdx.x * 256 + threadIdx.x;  // 0..32767
    int n = idx >> 7, wp = idx & 127;
    float x0 = W[n * 512 + 256 + wp * 2];
    float x1 = W[n * 512 + 257 + wp * 2];
    g_whi[idx] = pack_f16(x0, x1);
}

// ---------------------------------------------------------------------------
// c[b,k] = bias[k] + sum_h hidden[b,h] * W[k,h]
// ---------------------------------------------------------------------------
__global__ void compute_c_kernel(const float* __restrict__ hidden,
                                 const float* __restrict__ W,
                                 const float* __restrict__ bias) {
    __shared__ float hs[HID];
    int b = blockIdx.x;
    int k = threadIdx.x;
    hs[k] = hidden[b * HID + k];
    __syncthreads();
    float acc = bias[k];
    const float4* wr = (const float4*)(W + (size_t)k * (2 * HID));
#pragma unroll 8
    for (int h4 = 0; h4 < HID / 4; h4++) {
        float4 w = wr[h4];
        acc += w.x * hs[h4 * 4 + 0] + w.y * hs[h4 * 4 + 1]
             + w.z * hs[h4 * 4 + 2] + w.w * hs[h4 * 4 + 3];
    }
    g_c[b * HID + k] = acc;
}

// ---------------------------------------------------------------------------
// Main fused kernel: persistent CTAs. B resident in SMEM (loaded ONCE per CTA).
// Per tile: A load+convert (full coverage, R11-proven), barrier-free MMA loop,
// fused logits/tanh/v-dot epilogue + per-tile softmax stats + partial context.
// ---------------------------------------------------------------------------
__global__ void __launch_bounds__(256, 1) main_mma_kernel(
    const float* __restrict__ enc, const float* __restrict__ v,
    float* __restrict__ attn)
{
    extern __shared__ char smem[];
    const uint32_t S = cvta_smem(smem);

    int t = threadIdx.x;
    int lane = t & 31, w = t >> 5;
    int grp = lane >> 2, tig = lane & 3;
    int mbase = (w & 3) * 32;
    int nb    = (w >> 2) * 64;

    // ldmatrix lane addressing
    int lrow   = lane & 15;
    uint32_t ghalfA = (uint32_t)(lane >> 4);
    uint32_t sA     = (uint32_t)(lrow & 7);
    uint32_t aBase0 = S + SA_HI + (uint32_t)(mbase + lrow) * 512u;
    uint32_t aBase1 = aBase0 + 16u * 512u;
    uint32_t ghalfB = (uint32_t)((lane >> 3) & 1);
    uint32_t sBl    = (uint32_t)(lane & 7);
    uint32_t bRow0  = ((uint32_t)(nb + (lane & 7) + ((lane >> 4) & 1) * 8)) * 128u;

    // per-thread A staging: 2 threads per row, 128 floats each
    const int arow  = t >> 1;
    const int ahalf = t & 1;
    const uint32_t awbase = (uint32_t)arow * 128 + (uint32_t)ahalf * 64;
    const uint32_t asz    = ((uint32_t)arow & 7) << 2;

    ((float*)(smem + SVS))[t] = v[t];

    // ---- prefetch ALL of B (8 chunks x 16KB), ONCE per CTA ----
    {
        int n  = t >> 1;
        int wq = (t & 1) * 16;
        uint32_t sz   = ((uint32_t)n & 7) << 2;
        uint32_t wrow = (uint32_t)n * 32;
#pragma unroll
        for (int q = 0; q < 8; q++) {
            int p = q >> 2, cc = q & 3;
            uint32_t buf = S + SB + (uint32_t)q * 16384u;
            const uint32_t* src = g_whi + (size_t)(p * 128 + n) * 128 + cc * 32 + wq;
#pragma unroll
            for (int j = 0; j < 4; j++) {
                uint32_t wc = (uint32_t)(wq + j * 4);
                cp_async16(buf + ((wrow + (wc ^ sz)) << 2), src + j * 4);
            }
        }
        asm volatile("cp.async.commit_group;" ::: "memory");
        asm volatile("cp.async.wait_group 0;" ::: "memory");
    }

    float accF[2][8][4] = {};
    const float* cs_all = (const float*)(smem + SCS);
    const float* vs_all = (const float*)(smem + SVS);
    float* slog = (float*)(smem + SLOG);
    float* redm = (float*)(smem + SRED);
    float* reds = (float*)(smem + SRED + 16);
    float* es   = (float*)(smem + SES);

    for (int tile = blockIdx.x; tile < NTILES; tile += GRID_MAIN) {
        int b  = tile >> 6;
        size_t rowbase = (size_t)b * NS + (size_t)(tile & 63) * 128;

        // stage c[b,*], zero slog
        ((float*)(smem + SCS))[t] = g_c[b * HID + t];
        slog[t] = 0.f;

        // ---- A load + fp32->f16 convert + swizzled STS (FULL coverage) ----
        {
            const float4* src = ((const float4*)(enc + (rowbase + (size_t)arow) * HID)) + ahalf * 32;
#pragma unroll 4
            for (int j = 0; j < 16; j++) {
                float4 f0 = src[2 * j], f1 = src[2 * j + 1];
                uint32_t h0 = pack_f16(f0.x, f0.y);
                uint32_t h1 = pack_f16(f0.z, f0.w);
                uint32_t h2 = pack_f16(f1.x, f1.y);
                uint32_t h3 = pack_f16(f1.z, f1.w);
                uint32_t wd = awbase + (uint32_t)j * 4;
                sts128(S + SA_HI + ((wd ^ asz) << 2), h0, h1, h2, h3);
            }
        }
        __syncthreads();   // publishes A plane, SCS, slog (and B on first iter)

        // ---- MMA mainloop: 2 passes x 16 ksteps, no barriers ----
#pragma unroll 1
        for (int p = 0; p < 2; p++) {
#pragma unroll 1
            for (int cc = 0; cc < 4; cc++) {
                uint32_t Bbuf = S + SB + (uint32_t)(p * 4 + cc) * 16384u;
#pragma unroll
                for (int ks = 0; ks < 4; ks++) {
                    int kg = (cc << 2) + ks;
                    uint32_t offA = (((uint32_t)(2 * kg) + ghalfA) ^ sA) << 4;
                    uint32_t ah0[4], ah1[4];
                    LDM4(ah0, aBase0 + offA);
                    LDM4(ah1, aBase1 + offA);

                    uint32_t offB = (((uint32_t)(2 * ks) + ghalfB) ^ sBl) << 4;
                    uint32_t bh[4][4];
                    uint32_t bAh = Bbuf + bRow0 + offB;
#pragma unroll
                    for (int g = 0; g < 4; g++)
                        LDM4(bh[g], bAh + (uint32_t)g * 2048u);
#pragma unroll
                    for (int g = 0; g < 4; g++) {
#pragma unroll
                        for (int sub = 0; sub < 2; sub++) {
                            int ni = 2 * g + sub;
                            mma_f32(accF[0][ni], ah0, bh[g][2 * sub], bh[g][2 * sub + 1]);
                            mma_f32(accF[1][ni], ah1, bh[g][2 * sub], bh[g][2 * sub + 1]);
                        }
                    }
                }
            }

            // ---- pass epilogue ----
            const float* cs = cs_all + p * 128;
            const float* vs = vs_all + p * 128;
#pragma unroll
            for (int mi = 0; mi < 2; mi++) {
                float s0 = 0.f, s1 = 0.f;
#pragma unroll
                for (int ni = 0; ni < 8; ni++) {
                    int c0 = nb + ni * 8 + tig * 2;
                    float vv0 = vs[c0], vv1 = vs[c0 + 1];
                    float cc0 = cs[c0], cc1 = cs[c0 + 1];
                    s0 += vv0 * tanhf(accF[mi][ni][0] + cc0)
                        + vv1 * tanhf(accF[mi][ni][1] + cc1);
                    s1 += vv0 * tanhf(accF[mi][ni][2] + cc0)
                        + vv1 * tanhf(accF[mi][ni][3] + cc1);
#pragma unroll
                    for (int j = 0; j < 4; j++) accF[mi][ni][j] = 0.f;
                }
                s0 += __shfl_xor_sync(0xffffffffu, s0, 1);
                s0 += __shfl_xor_sync(0xffffffffu, s0, 2);
                s1 += __shfl_xor_sync(0xffffffffu, s1, 1);
                s1 += __shfl_xor_sync(0xffffffffu, s1, 2);
                if (tig == 0) {
                    int r0 = mbase + mi * 16 + grp;
                    slog[r0 * 2 + (w >> 2)]       += s0;
                    slog[(r0 + 8) * 2 + (w >> 2)] += s1;
                }
            }
        }
        __syncthreads();

        // ---- finalize logits, per-tile softmax stats ----
        float logit = 0.f;
        if (t < 128) {
            logit = slog[t * 2] + slog[t * 2 + 1];
            attn[rowbase + t] = logit;
            float m = logit;
#pragma unroll
            for (int off = 16; off > 0; off >>= 1)
                m = fmaxf(m, __shfl_xor_sync(0xffffffffu, m, off));
            if (lane == 0) redm[t >> 5] = m;
        }
        __syncthreads();
        float m_tile = fmaxf(fmaxf(redm[0], redm[1]), fmaxf(redm[2], redm[3]));
        if (t < 128) {
            float e = expf(logit - m_tile);
            es[t] = e;
            float se = e;
#pragma unroll
            for (int off = 16; off > 0; off >>= 1)
                se += __shfl_xor_sync(0xffffffffu, se, off);
            if (lane == 0) reds[t >> 5] = se;
        }
        __syncthreads();
        if (t == 0) {
            g_msum[tile * 2]     = m_tile;
            g_msum[tile * 2 + 1] = (reds[0] + reds[1]) + (reds[2] + reds[3]);
        }

        // ---- fused partial context: num[h] = sum_s e_s * enc_f16[s,h] ----
        {
            int wc = t & 127, sh = t >> 7;
            float nx = 0.f, ny = 0.f;
#pragma unroll 4
            for (int s5 = 0; s5 < 64; s5++) {
                int s = sh * 64 + s5;
                uint32_t ws = (uint32_t)s * 128u + ((uint32_t)wc ^ (((uint32_t)s & 7u) << 2));
                float2 f = h22f2(lds32(S + SA_HI + (ws << 2)));
                float e = es[s];
                nx += e * f.x;
                ny += e * f.y;
            }
            float2* comb = (float2*)(smem + SCOMB);
            comb[t] = make_float2(nx, ny);
            __syncthreads();   // comb ready AND all A-plane reads complete
            if (t < 128) {
                float2 a = comb[t], bb = comb[t + 128];
                ((float2*)(g_pctx + (size_t)tile * HID))[t] =
                    make_float2(a.x + bb.x, a.y + bb.y);
            }
        }
        // next iteration overwrites the A plane only after this point
    }
}

// ---------------------------------------------------------------------------
// softmax over S per batch, in place (1024 threads)
// ---------------------------------------------------------------------------
__global__ void softmax_kernel(float* __restrict__ attn) {
    __shared__ float red[1024];
    int b = blockIdx.x;
    int t = threadIdx.x;
    float4* row = (float4*)(attn + (size_t)b * NS);

    float mx = -1e30f;
    for (int i = t; i < NS / 4; i += 1024) {
        float4 x = row[i];
        mx = fmaxf(mx, fmaxf(fmaxf(x.x, x.y), fmaxf(x.z, x.w)));
    }
    red[t] = mx; __syncthreads();
    for (int o = 512; o > 0; o >>= 1) {
        if (t < o) red[t] = fmaxf(red[t], red[t + o]);
        __syncthreads();
    }
    mx = red[0];
    __syncthreads();

    float sum = 0.f;
    for (int i = t; i < NS / 4; i += 1024) {
        float4 x = row[i];
        x.x = expf(x.x - mx); x.y = expf(x.y - mx);
        x.z = expf(x.z - mx); x.w = expf(x.w - mx);
        row[i] = x;
        sum += (x.x + x.y) + (x.z + x.w);
    }
    red[t] = sum; __syncthreads();
    for (int o = 512; o > 0; o >>= 1) {
        if (t < o) red[t] += red[t + o];
        __syncthreads();
    }
    float inv = 1.f / red[0];
    for (int i = t; i < NS / 4; i += 1024) {
        float4 x = row[i];
        x.x *= inv; x.y *= inv; x.z *= inv; x.w *= inv;
        row[i] = x;
    }
}

// ---------------------------------------------------------------------------
// ctx_final: combine per-tile partial contexts with global-max rescale
// ---------------------------------------------------------------------------
__global__ void ctx_final_kernel(float* __restrict__ ctx) {
    __shared__ float sm[64], ss[64], sc[64];
    int b = blockIdx.x;
    int t = threadIdx.x;   // 256
    if (t < 64) {
        sm[t] = g_msum[(b * 64 + t) * 2];
        ss[t] = g_msum[(b * 64 + t) * 2 + 1];
    }
    __syncthreads();
    if (t == 0) {
        float M = sm[0];
#pragma unroll
        for (int i = 1; i < 64; i++) M = fmaxf(M, sm[i]);
        float D = 0.f;
        for (int i = 0; i < 64; i++) {
            float sci = expf(sm[i] - M);
            sc[i] = sci;
            D += sci * ss[i];
        }
        float invD = 1.f / D;
        for (int i = 0; i < 64; i++) sc[i] *= invD;
    }
    __syncthreads();
    float acc = 0.f;
#pragma unroll 8
    for (int i = 0; i < 64; i++)
        acc += sc[i] * g_pctx[(size_t)(b * 64 + i) * HID + t];
    ctx[b * HID + t] = acc;
}

// ---------------------------------------------------------------------------
extern "C" void kernel_launch(void* const* d_in, const int* in_sizes, int n_in,
                              void* d_out, int out_size) {
    const float* hidden = (const float*)d_in[0];  // (1,32,256)
    const float* enc    = (const float*)d_in[1];  // (32,8192,256)
    const float* W      = (const float*)d_in[2];  // (256,512)
    const float* bias   = (const float*)d_in[3];  // (256,)
    const float* v      = (const float*)d_in[4];  // (256,)

    float* out  = (float*)d_out;
    float* ctx  = out;            // (32,256) first
    float* attn = out + NB * HID; // (32,8192) second

    cudaFuncSetAttribute(main_mma_kernel,
                         cudaFuncAttributeMaxDynamicSharedMemorySize, SMEM_MAIN);

    prep_w_kernel<<<128, 256>>>(W);
    compute_c_kernel<<<NB, HID>>>(hidden, W, bias);
    main_mma_kernel<<<GRID_MAIN, 256, SMEM_MAIN>>>(enc, v, attn);
    softmax_kernel<<<NB, 1024>>>(attn);
    ctx_final_kernel<<<NB, 256>>>(ctx);
}

// round 15
// speedup vs baseline: 2.0190x; 1.0618x over previous
#include <cuda_runtime.h>
#include <cuda_fp16.h>
#include <cstdint>

#define HID 256
#define NB 32
#define NS 8192
#define NTILES 2048
#define GRID_MAIN 148

// SMEM byte offsets (main kernel)
#define SA_HI 0          // A plane: 128 rows x 512B (f16) = 64KB
#define SB    65536      // B resident: 8 chunks x 16KB = 128KB (persistent)
#define SCS   196608     // c[b,*] 1KB
#define SVS   197632     // v 1KB
#define SLOG  198656     // 128 rows x 2 slots floats = 1KB
#define SES   199680     // 128 exp values = 512B
#define SRED  200192     // reduce scratch
#define SCOMB 200704     // ctx combine scratch: 256 float4 = 4KB
#define SMEM_MAIN 204800

__device__ float    g_c[NB * HID];
__device__ uint32_t g_whi[HID * 128];     // We f16, [k_out][h/2] f16x2
__device__ float    g_pctx[NTILES * HID]; // per-tile unnormalized context
__device__ float    g_msum[NTILES * 2];   // per-tile (max, sum_exp)

// ---------------- helpers ----------------
__device__ __forceinline__ uint32_t cvta_smem(const void* p) {
    uint32_t a;
    asm("{ .reg .u64 t; cvta.to.shared.u64 t, %1; cvt.u32.u64 %0, t; }" : "=r"(a) : "l"(p));
    return a;
}
__device__ __forceinline__ uint32_t pack_f16(float x0, float x1) {
    uint32_t r;
    asm("cvt.rn.f16x2.f32 %0, %1, %2;" : "=r"(r) : "f"(x1), "f"(x0));
    return r;
}
__device__ __forceinline__ void sts128(uint32_t a, uint32_t x, uint32_t y, uint32_t z, uint32_t w) {
    asm volatile("st.shared.v4.b32 [%0], {%1,%2,%3,%4};" :: "r"(a), "r"(x), "r"(y), "r"(z), "r"(w) : "memory");
}
__device__ __forceinline__ void cp_async16(uint32_t saddr, const void* gptr) {
    uint64_t g;
    asm("cvta.to.global.u64 %0, %1;" : "=l"(g) : "l"(gptr));
    asm volatile("cp.async.cg.shared.global [%0], [%1], 16;" :: "r"(saddr), "l"(g) : "memory");
}
// fp16 x fp16, fp32 accumulate
__device__ __forceinline__ void mma_f32(float* c,
        const uint32_t* a, uint32_t b0, uint32_t b1) {
    asm("mma.sync.aligned.m16n8k16.row.col.f32.f16.f16.f32 "
        "{%0,%1,%2,%3}, {%4,%5,%6,%7}, {%8,%9}, {%0,%1,%2,%3};"
        : "+f"(c[0]), "+f"(c[1]), "+f"(c[2]), "+f"(c[3])
        : "r"(a[0]), "r"(a[1]), "r"(a[2]), "r"(a[3]), "r"(b0), "r"(b1));
}
#define LDM4(r, a) \
    asm volatile("ldmatrix.sync.aligned.m8n8.x4.shared.b16 {%0,%1,%2,%3}, [%4];" \
        : "=r"((r)[0]), "=r"((r)[1]), "=r"((r)[2]), "=r"((r)[3]) : "r"(a))

// one N-pass of 16 ksteps (pass selects B half)
__device__ __forceinline__ void mma_pass(uint32_t S, int pass,
        uint32_t aBase0, uint32_t aBase1, uint32_t ghalfA, uint32_t sA,
        uint32_t ghalfB, uint32_t sBl, uint32_t bRow0, float accF[2][8][4])
{
#pragma unroll 1
    for (int cc = 0; cc < 4; cc++) {
        uint32_t Bbuf = S + SB + (uint32_t)(pass * 4 + cc) * 16384u;
#pragma unroll
        for (int ks = 0; ks < 4; ks++) {
            int kg = (cc << 2) + ks;
            uint32_t offA = (((uint32_t)(2 * kg) + ghalfA) ^ sA) << 4;
            uint32_t ah0[4], ah1[4];
            LDM4(ah0, aBase0 + offA);
            LDM4(ah1, aBase1 + offA);

            uint32_t offB = (((uint32_t)(2 * ks) + ghalfB) ^ sBl) << 4;
            uint32_t bh[4][4];
            uint32_t bAh = Bbuf + bRow0 + offB;
#pragma unroll
            for (int g = 0; g < 4; g++)
                LDM4(bh[g], bAh + (uint32_t)g * 2048u);
#pragma unroll
            for (int g = 0; g < 4; g++) {
#pragma unroll
                for (int sub = 0; sub < 2; sub++) {
                    int ni = 2 * g + sub;
                    mma_f32(accF[0][ni], ah0, bh[g][2 * sub], bh[g][2 * sub + 1]);
                    mma_f32(accF[1][ni], ah1, bh[g][2 * sub], bh[g][2 * sub + 1]);
                }
            }
        }
    }
}

// ---------------------------------------------------------------------------
// prep: We[k,h] = W[k, 256+h] -> single f16 plane, [k][h/2] f16x2
// ---------------------------------------------------------------------------
__global__ void prep_w_kernel(const float* __restrict__ W) {
    int idx = blockIdx.x * 256 + threadIdx.x;  // 0..32767
    int n = idx >> 7, wp = idx & 127;
    float x0 = W[n * 512 + 256 + wp * 2];
    float x1 = W[n * 512 + 257 + wp * 2];
    g_whi[idx] = pack_f16(x0, x1);
}

// ---------------------------------------------------------------------------
// c[b,k] = bias[k] + sum_h hidden[b,h] * W[k,h]
// ---------------------------------------------------------------------------
__global__ void compute_c_kernel(const float* __restrict__ hidden,
                                 const float* __restrict__ W,
                                 const float* __restrict__ bias) {
    __shared__ float hs[HID];
    int b = blockIdx.x;
    int k = threadIdx.x;
    hs[k] = hidden[b * HID + k];
    __syncthreads();
    float acc = bias[k];
    const float4* wr = (const float4*)(W + (size_t)k * (2 * HID));
#pragma unroll 8
    for (int h4 = 0; h4 < HID / 4; h4++) {
        float4 w = wr[h4];
        acc += w.x * hs[h4 * 4 + 0] + w.y * hs[h4 * 4 + 1]
             + w.z * hs[h4 * 4 + 2] + w.w * hs[h4 * 4 + 3];
    }
    g_c[b * HID + k] = acc;
}

// ---------------------------------------------------------------------------
// Main fused kernel: persistent CTAs, resident B, next-tile A prefetch
// interleaved with the pass-1 tanh epilogue. ctx-partial reads fp32 enc.
// ---------------------------------------------------------------------------
__global__ void __launch_bounds__(256, 1) main_mma_kernel(
    const float* __restrict__ enc, const float* __restrict__ v,
    float* __restrict__ attn)
{
    extern __shared__ char smem[];
    const uint32_t S = cvta_smem(smem);

    int t = threadIdx.x;
    int lane = t & 31, w = t >> 5;
    int grp = lane >> 2, tig = lane & 3;
    int mbase = (w & 3) * 32;
    int nb    = (w >> 2) * 64;

    // ldmatrix lane addressing
    int lrow   = lane & 15;
    uint32_t ghalfA = (uint32_t)(lane >> 4);
    uint32_t sA     = (uint32_t)(lrow & 7);
    uint32_t aBase0 = S + SA_HI + (uint32_t)(mbase + lrow) * 512u;
    uint32_t aBase1 = aBase0 + 16u * 512u;
    uint32_t ghalfB = (uint32_t)((lane >> 3) & 1);
    uint32_t sBl    = (uint32_t)(lane & 7);
    uint32_t bRow0  = ((uint32_t)(nb + (lane & 7) + ((lane >> 4) & 1) * 8)) * 128u;

    // per-thread A staging: 2 threads per row, 128 floats each
    const int arow  = t >> 1;
    const int ahalf = t & 1;
    const uint32_t awbase = (uint32_t)arow * 128 + (uint32_t)ahalf * 64;
    const uint32_t asz    = ((uint32_t)arow & 7) << 2;

    ((float*)(smem + SVS))[t] = v[t];

    // ---- prefetch ALL of B (8 chunks x 16KB), ONCE per CTA ----
    {
        int n  = t >> 1;
        int wq = (t & 1) * 16;
        uint32_t sz   = ((uint32_t)n & 7) << 2;
        uint32_t wrow = (uint32_t)n * 32;
#pragma unroll
        for (int q = 0; q < 8; q++) {
            int p = q >> 2, cc = q & 3;
            uint32_t buf = S + SB + (uint32_t)q * 16384u;
            const uint32_t* src = g_whi + (size_t)(p * 128 + n) * 128 + cc * 32 + wq;
#pragma unroll
            for (int j = 0; j < 4; j++) {
                uint32_t wc = (uint32_t)(wq + j * 4);
                cp_async16(buf + ((wrow + (wc ^ sz)) << 2), src + j * 4);
            }
        }
        asm volatile("cp.async.commit_group;" ::: "memory");
        asm volatile("cp.async.wait_group 0;" ::: "memory");
    }

    // ---- load + convert + STS A for FIRST tile ----
    {
        int tile0 = blockIdx.x;
        size_t rb0 = (size_t)(tile0 >> 6) * NS + (size_t)(tile0 & 63) * 128;
        const float4* src = ((const float4*)(enc + (rb0 + (size_t)arow) * HID)) + ahalf * 32;
#pragma unroll 4
        for (int j = 0; j < 16; j++) {
            float4 f0 = src[2 * j], f1 = src[2 * j + 1];
            uint32_t h0 = pack_f16(f0.x, f0.y);
            uint32_t h1 = pack_f16(f0.z, f0.w);
            uint32_t h2 = pack_f16(f1.x, f1.y);
            uint32_t h3 = pack_f16(f1.z, f1.w);
            uint32_t wd = awbase + (uint32_t)j * 4;
            sts128(S + SA_HI + ((wd ^ asz) << 2), h0, h1, h2, h3);
        }
    }

    float accF[2][8][4] = {};
    const float* cs_all = (const float*)(smem + SCS);
    const float* vs_all = (const float*)(smem + SVS);
    float* slog = (float*)(smem + SLOG);
    float* redm = (float*)(smem + SRED);
    float* reds = (float*)(smem + SRED + 16);
    float* es   = (float*)(smem + SES);

    for (int tile = blockIdx.x; tile < NTILES; tile += GRID_MAIN) {
        int b  = tile >> 6;
        size_t rowbase = (size_t)b * NS + (size_t)(tile & 63) * 128;
        int next = tile + GRID_MAIN;
        bool has_next = (next < NTILES);

        // stage c[b,*], zero slog; barrier publishes these AND the A plane
        ((float*)(smem + SCS))[t] = g_c[b * HID + t];
        slog[t] = 0.f;
        __syncthreads();

        // ---- pass 0: MMA + full epilogue ----
        mma_pass(S, 0, aBase0, aBase1, ghalfA, sA, ghalfB, sBl, bRow0, accF);
        {
            const float* cs = cs_all;
            const float* vs = vs_all;
#pragma unroll
            for (int mi = 0; mi < 2; mi++) {
                float s0 = 0.f, s1 = 0.f;
#pragma unroll
                for (int ni = 0; ni < 8; ni++) {
                    int c0 = nb + ni * 8 + tig * 2;
                    float vv0 = vs[c0], vv1 = vs[c0 + 1];
                    float cc0 = cs[c0], cc1 = cs[c0 + 1];
                    s0 += vv0 * tanhf(accF[mi][ni][0] + cc0)
                        + vv1 * tanhf(accF[mi][ni][1] + cc1);
                    s1 += vv0 * tanhf(accF[mi][ni][2] + cc0)
                        + vv1 * tanhf(accF[mi][ni][3] + cc1);
#pragma unroll
                    for (int j = 0; j < 4; j++) accF[mi][ni][j] = 0.f;
                }
                s0 += __shfl_xor_sync(0xffffffffu, s0, 1);
                s0 += __shfl_xor_sync(0xffffffffu, s0, 2);
                s1 += __shfl_xor_sync(0xffffffffu, s1, 1);
                s1 += __shfl_xor_sync(0xffffffffu, s1, 2);
                if (tig == 0) {
                    int r0 = mbase + mi * 16 + grp;
                    slog[r0 * 2 + (w >> 2)]       += s0;
                    slog[(r0 + 8) * 2 + (w >> 2)] += s1;
                }
            }
        }

        // ---- pass 1: MMA ----
        mma_pass(S, 1, aBase0, aBase1, ghalfA, sA, ghalfB, sBl, bRow0, accF);
        __syncthreads();   // all A-plane ldmatrix reads complete

        // ---- pass-1 epilogue INTERLEAVED with next-tile A prefetch ----
        {
            const float4* srcn = nullptr;
            if (has_next) {
                size_t rbn = (size_t)(next >> 6) * NS + (size_t)(next & 63) * 128;
                srcn = ((const float4*)(enc + (rbn + (size_t)arow) * HID)) + ahalf * 32;
            }
            const float* cs = cs_all + 128;
            const float* vs = vs_all + 128;
            float s0m[2] = {0.f, 0.f}, s1m[2] = {0.f, 0.f};
#pragma unroll
            for (int ch = 0; ch < 4; ch++) {
                float4 fr[8];
                if (has_next) {
#pragma unroll
                    for (int j = 0; j < 8; j++) fr[j] = srcn[ch * 8 + j];
                }
                // epilogue slice: ni in [2ch, 2ch+2)
#pragma unroll
                for (int mi = 0; mi < 2; mi++) {
#pragma unroll
                    for (int nn = 0; nn < 2; nn++) {
                        int ni = 2 * ch + nn;
                        int c0 = nb + ni * 8 + tig * 2;
                        float vv0 = vs[c0], vv1 = vs[c0 + 1];
                        float cc0 = cs[c0], cc1 = cs[c0 + 1];
                        s0m[mi] += vv0 * tanhf(accF[mi][ni][0] + cc0)
                                 + vv1 * tanhf(accF[mi][ni][1] + cc1);
                        s1m[mi] += vv0 * tanhf(accF[mi][ni][2] + cc0)
                                 + vv1 * tanhf(accF[mi][ni][3] + cc1);
#pragma unroll
                        for (int j = 0; j < 4; j++) accF[mi][ni][j] = 0.f;
                    }
                }
                if (has_next) {
#pragma unroll
                    for (int jj = 0; jj < 4; jj++) {
                        float4 f0 = fr[2 * jj], f1 = fr[2 * jj + 1];
                        uint32_t h0 = pack_f16(f0.x, f0.y);
                        uint32_t h1 = pack_f16(f0.z, f0.w);
                        uint32_t h2 = pack_f16(f1.x, f1.y);
                        uint32_t h3 = pack_f16(f1.z, f1.w);
                        uint32_t wd = awbase + (uint32_t)(ch * 4 + jj) * 4;
                        sts128(S + SA_HI + ((wd ^ asz) << 2), h0, h1, h2, h3);
                    }
                }
            }
#pragma unroll
            for (int mi = 0; mi < 2; mi++) {
                float s0 = s0m[mi], s1 = s1m[mi];
                s0 += __shfl_xor_sync(0xffffffffu, s0, 1);
                s0 += __shfl_xor_sync(0xffffffffu, s0, 2);
                s1 += __shfl_xor_sync(0xffffffffu, s1, 1);
                s1 += __shfl_xor_sync(0xffffffffu, s1, 2);
                if (tig == 0) {
                    int r0 = mbase + mi * 16 + grp;
                    slog[r0 * 2 + (w >> 2)]       += s0;
                    slog[(r0 + 8) * 2 + (w >> 2)] += s1;
                }
            }
        }
        __syncthreads();

        // ---- finalize logits, per-tile softmax stats ----
        float logit = 0.f;
        if (t < 128) {
            logit = slog[t * 2] + slog[t * 2 + 1];
            attn[rowbase + t] = logit;
            float m = logit;
#pragma unroll
            for (int off = 16; off > 0; off >>= 1)
                m = fmaxf(m, __shfl_xor_sync(0xffffffffu, m, off));
            if (lane == 0) redm[t >> 5] = m;
        }
        __syncthreads();
        float m_tile = fmaxf(fmaxf(redm[0], redm[1]), fmaxf(redm[2], redm[3]));
        if (t < 128) {
            float e = expf(logit - m_tile);
            es[t] = e;
            float se = e;
#pragma unroll
            for (int off = 16; off > 0; off >>= 1)
                se += __shfl_xor_sync(0xffffffffu, se, off);
            if (lane == 0) reds[t >> 5] = se;
        }
        __syncthreads();   // publishes es[] to all threads
        if (t == 0) {
            g_msum[tile * 2]     = m_tile;
            g_msum[tile * 2 + 1] = (reds[0] + reds[1]) + (reds[2] + reds[3]);
        }

        // ---- partial context from GLOBAL fp32 enc (L2-hot): num = sum e_s*enc ----
        {
            int h4 = t & 63, sg = t >> 6;
            const float4* e4 = (const float4*)(enc + rowbase * HID);
            float4 a4 = make_float4(0.f, 0.f, 0.f, 0.f);
#pragma unroll 4
            for (int s = sg; s < 128; s += 4) {
                float e = es[s];
                float4 x = e4[(size_t)s * 64 + h4];
                a4.x += e * x.x; a4.y += e * x.y;
                a4.z += e * x.z; a4.w += e * x.w;
            }
            float4* comb = (float4*)(smem + SCOMB);
            comb[t] = a4;
            __syncthreads();
            if (t < 64) {
                float4 a = comb[t], bq = comb[t + 64], c = comb[t + 128], d = comb[t + 192];
                float4 r;
                r.x = (a.x + bq.x) + (c.x + d.x);
                r.y = (a.y + bq.y) + (c.y + d.y);
                r.z = (a.z + bq.z) + (c.z + d.z);
                r.w = (a.w + bq.w) + (c.w + d.w);
                ((float4*)(g_pctx + (size_t)tile * HID))[t] = r;
            }
        }
        // next loop-top barrier publishes the already-written next A plane
    }
}

// ---------------------------------------------------------------------------
// finalize: per-batch (M, D) from per-tile stats, normalize logits -> attn
// weights, and combine per-tile partial contexts. Replaces softmax + ctx_final.
// ---------------------------------------------------------------------------
__global__ void finalize_kernel(float* __restrict__ attn, float* __restrict__ ctx) {
    __shared__ float sc[64];
    __shared__ float sMD[2];
    int b = blockIdx.x;
    int t = threadIdx.x;   // 1024

    if (t == 0) {
        float M = -1e30f;
#pragma unroll
        for (int i = 0; i < 64; i++)
            M = fmaxf(M, g_msum[(b * 64 + i) * 2]);
        float D = 0.f;
        for (int i = 0; i < 64; i++) {
            float sci = expf(g_msum[(b * 64 + i) * 2] - M);
            sc[i] = sci;
            D += sci * g_msum[(b * 64 + i) * 2 + 1];
        }
        float invD = 1.f / D;
        for (int i = 0; i < 64; i++) sc[i] *= invD;
        sMD[0] = M; sMD[1] = invD;
    }
    __syncthreads();
    float M = sMD[0], invD = sMD[1];

    // normalize logits -> attention weights
    float4* row = (float4*)(attn + (size_t)b * NS);
#pragma unroll
    for (int i = t; i < NS / 4; i += 1024) {
        float4 x = row[i];
        x.x = expf(x.x - M) * invD;
        x.y = expf(x.y - M) * invD;
        x.z = expf(x.z - M) * invD;
        x.w = expf(x.w - M) * invD;
        row[i] = x;
    }

    // combine partial contexts
    if (t < HID) {
        float acc = 0.f;
#pragma unroll 8
        for (int i = 0; i < 64; i++)
            acc += sc[i] * g_pctx[(size_t)(b * 64 + i) * HID + t];
        ctx[b * HID + t] = acc;
    }
}

// ---------------------------------------------------------------------------
extern "C" void kernel_launch(void* const* d_in, const int* in_sizes, int n_in,
                              void* d_out, int out_size) {
    const float* hidden = (const float*)d_in[0];  // (1,32,256)
    const float* enc    = (const float*)d_in[1];  // (32,8192,256)
    const float* W      = (const float*)d_in[2];  // (256,512)
    const float* bias   = (const float*)d_in[3];  // (256,)
    const float* v      = (const float*)d_in[4];  // (256,)

    float* out  = (float*)d_out;
    float* ctx  = out;            // (32,256) first
    float* attn = out + NB * HID; // (32,8192) second

    cudaFuncSetAttribute(main_mma_kernel,
                         cudaFuncAttributeMaxDynamicSharedMemorySize, SMEM_MAIN);

    prep_w_kernel<<<128, 256>>>(W);
    compute_c_kernel<<<NB, HID>>>(hidden, W, bias);
    main_mma_kernel<<<GRID_MAIN, 256, SMEM_MAIN>>>(enc, v, attn);
    finalize_kernel<<<NB, 1024>>>(attn, ctx);
}

// round 16
// speedup vs baseline: 2.0678x; 1.0242x over previous
#include <cuda_runtime.h>
#include <cuda_fp16.h>
#include <cstdint>

#define HID 256
#define NB 32
#define NS 8192
#define NTILES 2048
#define GRID_MAIN 148

// SMEM byte offsets (main kernel)
#define SA_HI 0          // A plane: 128 rows x 512B (f16) = 64KB
#define SB    65536      // B resident: 8 chunks x 16KB = 128KB (persistent)
#define SCS   196608     // c[b,*] 1KB
#define SVS   197632     // v 1KB
#define SLOG  198656     // 128 rows x 2 slots floats = 1KB
#define SES   199680     // 128 exp values = 512B
#define SRED  200192     // reduce scratch
#define SCOMB 200704     // ctx combine scratch: 256 float4 = 4KB
#define SMEM_MAIN 204800

__device__ float    g_c[NB * HID];
__device__ uint32_t g_whi[HID * 128];     // We f16, [k_out][h/2] f16x2
__device__ float    g_pctx[NTILES * HID]; // per-tile unnormalized context
__device__ float    g_msum[NTILES * 2];   // per-tile (max, sum_exp)

// ---------------- helpers ----------------
__device__ __forceinline__ uint32_t cvta_smem(const void* p) {
    uint32_t a;
    asm("{ .reg .u64 t; cvta.to.shared.u64 t, %1; cvt.u32.u64 %0, t; }" : "=r"(a) : "l"(p));
    return a;
}
__device__ __forceinline__ uint32_t pack_f16(float x0, float x1) {
    uint32_t r;
    asm("cvt.rn.f16x2.f32 %0, %1, %2;" : "=r"(r) : "f"(x1), "f"(x0));
    return r;
}
__device__ __forceinline__ void sts128(uint32_t a, uint32_t x, uint32_t y, uint32_t z, uint32_t w) {
    asm volatile("st.shared.v4.b32 [%0], {%1,%2,%3,%4};" :: "r"(a), "r"(x), "r"(y), "r"(z), "r"(w) : "memory");
}
__device__ __forceinline__ void cp_async16(uint32_t saddr, const void* gptr) {
    uint64_t g;
    asm("cvta.to.global.u64 %0, %1;" : "=l"(g) : "l"(gptr));
    asm volatile("cp.async.cg.shared.global [%0], [%1], 16;" :: "r"(saddr), "l"(g) : "memory");
}
// fast, accurate tanh: err ~1e-6 (EX2 + fast divide), no fast-math needed
__device__ __forceinline__ float fast_tanh(float x) {
    float e = __expf(-2.0f * fabsf(x));
    float t = __fdividef(1.0f - e, 1.0f + e);
    return copysignf(t, x);
}
// fp16 x fp16, fp32 accumulate
__device__ __forceinline__ void mma_f32(float* c,
        const uint32_t* a, uint32_t b0, uint32_t b1) {
    asm("mma.sync.aligned.m16n8k16.row.col.f32.f16.f16.f32 "
        "{%0,%1,%2,%3}, {%4,%5,%6,%7}, {%8,%9}, {%0,%1,%2,%3};"
        : "+f"(c[0]), "+f"(c[1]), "+f"(c[2]), "+f"(c[3])
        : "r"(a[0]), "r"(a[1]), "r"(a[2]), "r"(a[3]), "r"(b0), "r"(b1));
}
#define LDM4(r, a) \
    asm volatile("ldmatrix.sync.aligned.m8n8.x4.shared.b16 {%0,%1,%2,%3}, [%4];" \
        : "=r"((r)[0]), "=r"((r)[1]), "=r"((r)[2]), "=r"((r)[3]) : "r"(a))

// one N-pass of 16 ksteps (pass selects B half)
__device__ __forceinline__ void mma_pass(uint32_t S, int pass,
        uint32_t aBase0, uint32_t aBase1, uint32_t ghalfA, uint32_t sA,
        uint32_t ghalfB, uint32_t sBl, uint32_t bRow0, float accF[2][8][4])
{
#pragma unroll 1
    for (int cc = 0; cc < 4; cc++) {
        uint32_t Bbuf = S + SB + (uint32_t)(pass * 4 + cc) * 16384u;
#pragma unroll
        for (int ks = 0; ks < 4; ks++) {
            int kg = (cc << 2) + ks;
            uint32_t offA = (((uint32_t)(2 * kg) + ghalfA) ^ sA) << 4;
            uint32_t ah0[4], ah1[4];
            LDM4(ah0, aBase0 + offA);
            LDM4(ah1, aBase1 + offA);

            uint32_t offB = (((uint32_t)(2 * ks) + ghalfB) ^ sBl) << 4;
            uint32_t bh[4][4];
            uint32_t bAh = Bbuf + bRow0 + offB;
#pragma unroll
            for (int g = 0; g < 4; g++)
                LDM4(bh[g], bAh + (uint32_t)g * 2048u);
#pragma unroll
            for (int g = 0; g < 4; g++) {
#pragma unroll
                for (int sub = 0; sub < 2; sub++) {
                    int ni = 2 * g + sub;
                    mma_f32(accF[0][ni], ah0, bh[g][2 * sub], bh[g][2 * sub + 1]);
                    mma_f32(accF[1][ni], ah1, bh[g][2 * sub], bh[g][2 * sub + 1]);
                }
            }
        }
    }
}

// ---------------------------------------------------------------------------
// merged prep: blocks [0,128) convert We -> f16 plane; blocks [128,160)
// compute c[b,k] = bias[k] + sum_h hidden[b,h] * W[k,h]
// ---------------------------------------------------------------------------
__global__ void prep_kernel(const float* __restrict__ W,
                            const float* __restrict__ hidden,
                            const float* __restrict__ bias) {
    __shared__ float hs[HID];
    int t = threadIdx.x;
    if (blockIdx.x < 128) {
        int idx = blockIdx.x * 256 + t;  // 0..32767
        int n = idx >> 7, wp = idx & 127;
        float x0 = W[n * 512 + 256 + wp * 2];
        float x1 = W[n * 512 + 257 + wp * 2];
        g_whi[idx] = pack_f16(x0, x1);
    } else {
        int b = blockIdx.x - 128;
        hs[t] = hidden[b * HID + t];
        __syncthreads();
        float acc = bias[t];
        const float4* wr = (const float4*)(W + (size_t)t * (2 * HID));
#pragma unroll 8
        for (int h4 = 0; h4 < HID / 4; h4++) {
            float4 w = wr[h4];
            acc += w.x * hs[h4 * 4 + 0] + w.y * hs[h4 * 4 + 1]
                 + w.z * hs[h4 * 4 + 2] + w.w * hs[h4 * 4 + 3];
        }
        g_c[b * HID + t] = acc;
    }
}

// ---------------------------------------------------------------------------
// Main fused kernel: persistent CTAs, resident B, next-tile A prefetch
// interleaved with the pass-1 tanh epilogue. ctx-partial reads fp32 enc.
// ---------------------------------------------------------------------------
__global__ void __launch_bounds__(256, 1) main_mma_kernel(
    const float* __restrict__ enc, const float* __restrict__ v,
    float* __restrict__ attn)
{
    extern __shared__ char smem[];
    const uint32_t S = cvta_smem(smem);

    int t = threadIdx.x;
    int lane = t & 31, w = t >> 5;
    int grp = lane >> 2, tig = lane & 3;
    int mbase = (w & 3) * 32;
    int nb    = (w >> 2) * 64;

    // ldmatrix lane addressing
    int lrow   = lane & 15;
    uint32_t ghalfA = (uint32_t)(lane >> 4);
    uint32_t sA     = (uint32_t)(lrow & 7);
    uint32_t aBase0 = S + SA_HI + (uint32_t)(mbase + lrow) * 512u;
    uint32_t aBase1 = aBase0 + 16u * 512u;
    uint32_t ghalfB = (uint32_t)((lane >> 3) & 1);
    uint32_t sBl    = (uint32_t)(lane & 7);
    uint32_t bRow0  = ((uint32_t)(nb + (lane & 7) + ((lane >> 4) & 1) * 8)) * 128u;

    // per-thread A staging: 2 threads per row, 128 floats each
    const int arow  = t >> 1;
    const int ahalf = t & 1;
    const uint32_t awbase = (uint32_t)arow * 128 + (uint32_t)ahalf * 64;
    const uint32_t asz    = ((uint32_t)arow & 7) << 2;

    ((float*)(smem + SVS))[t] = v[t];

    // ---- prefetch ALL of B (8 chunks x 16KB), ONCE per CTA ----
    {
        int n  = t >> 1;
        int wq = (t & 1) * 16;
        uint32_t sz   = ((uint32_t)n & 7) << 2;
        uint32_t wrow = (uint32_t)n * 32;
#pragma unroll
        for (int q = 0; q < 8; q++) {
            int p = q >> 2, cc = q & 3;
            uint32_t buf = S + SB + (uint32_t)q * 16384u;
            const uint32_t* src = g_whi + (size_t)(p * 128 + n) * 128 + cc * 32 + wq;
#pragma unroll
            for (int j = 0; j < 4; j++) {
                uint32_t wc = (uint32_t)(wq + j * 4);
                cp_async16(buf + ((wrow + (wc ^ sz)) << 2), src + j * 4);
            }
        }
        asm volatile("cp.async.commit_group;" ::: "memory");
        asm volatile("cp.async.wait_group 0;" ::: "memory");
    }

    // ---- load + convert + STS A for FIRST tile ----
    {
        int tile0 = blockIdx.x;
        size_t rb0 = (size_t)(tile0 >> 6) * NS + (size_t)(tile0 & 63) * 128;
        const float4* src = ((const float4*)(enc + (rb0 + (size_t)arow) * HID)) + ahalf * 32;
#pragma unroll 4
        for (int j = 0; j < 16; j++) {
            float4 f0 = src[2 * j], f1 = src[2 * j + 1];
            uint32_t h0 = pack_f16(f0.x, f0.y);
            uint32_t h1 = pack_f16(f0.z, f0.w);
            uint32_t h2 = pack_f16(f1.x, f1.y);
            uint32_t h3 = pack_f16(f1.z, f1.w);
            uint32_t wd = awbase + (uint32_t)j * 4;
            sts128(S + SA_HI + ((wd ^ asz) << 2), h0, h1, h2, h3);
        }
    }

    float accF[2][8][4] = {};
    const float* cs_all = (const float*)(smem + SCS);
    const float* vs_all = (const float*)(smem + SVS);
    float* slog = (float*)(smem + SLOG);
    float* redm = (float*)(smem + SRED);
    float* reds = (float*)(smem + SRED + 16);
    float* es   = (float*)(smem + SES);

    for (int tile = blockIdx.x; tile < NTILES; tile += GRID_MAIN) {
        int b  = tile >> 6;
        size_t rowbase = (size_t)b * NS + (size_t)(tile & 63) * 128;
        int next = tile + GRID_MAIN;
        bool has_next = (next < NTILES);

        // stage c[b,*], zero slog; barrier publishes these AND the A plane
        ((float*)(smem + SCS))[t] = g_c[b * HID + t];
        slog[t] = 0.f;
        __syncthreads();

        // ---- pass 0: MMA + full epilogue ----
        mma_pass(S, 0, aBase0, aBase1, ghalfA, sA, ghalfB, sBl, bRow0, accF);
        {
            const float* cs = cs_all;
            const float* vs = vs_all;
#pragma unroll
            for (int mi = 0; mi < 2; mi++) {
                float s0 = 0.f, s1 = 0.f;
#pragma unroll
                for (int ni = 0; ni < 8; ni++) {
                    int c0 = nb + ni * 8 + tig * 2;
                    float vv0 = vs[c0], vv1 = vs[c0 + 1];
                    float cc0 = cs[c0], cc1 = cs[c0 + 1];
                    s0 += vv0 * fast_tanh(accF[mi][ni][0] + cc0)
                        + vv1 * fast_tanh(accF[mi][ni][1] + cc1);
                    s1 += vv0 * fast_tanh(accF[mi][ni][2] + cc0)
                        + vv1 * fast_tanh(accF[mi][ni][3] + cc1);
#pragma unroll
                    for (int j = 0; j < 4; j++) accF[mi][ni][j] = 0.f;
                }
                s0 += __shfl_xor_sync(0xffffffffu, s0, 1);
                s0 += __shfl_xor_sync(0xffffffffu, s0, 2);
                s1 += __shfl_xor_sync(0xffffffffu, s1, 1);
                s1 += __shfl_xor_sync(0xffffffffu, s1, 2);
                if (tig == 0) {
                    int r0 = mbase + mi * 16 + grp;
                    slog[r0 * 2 + (w >> 2)]       += s0;
                    slog[(r0 + 8) * 2 + (w >> 2)] += s1;
                }
            }
        }

        // ---- pass 1: MMA ----
        mma_pass(S, 1, aBase0, aBase1, ghalfA, sA, ghalfB, sBl, bRow0, accF);
        __syncthreads();   // all A-plane ldmatrix reads complete

        // ---- pass-1 epilogue INTERLEAVED with next-tile A prefetch ----
        {
            const float4* srcn = nullptr;
            if (has_next) {
                size_t rbn = (size_t)(next >> 6) * NS + (size_t)(next & 63) * 128;
                srcn = ((const float4*)(enc + (rbn + (size_t)arow) * HID)) + ahalf * 32;
            }
            const float* cs = cs_all + 128;
            const float* vs = vs_all + 128;
            float s0m[2] = {0.f, 0.f}, s1m[2] = {0.f, 0.f};
#pragma unroll
            for (int ch = 0; ch < 4; ch++) {
                float4 fr[8];
                if (has_next) {
#pragma unroll
                    for (int j = 0; j < 8; j++) fr[j] = srcn[ch * 8 + j];
                }
                // epilogue slice: ni in [2ch, 2ch+2)
#pragma unroll
                for (int mi = 0; mi < 2; mi++) {
#pragma unroll
                    for (int nn = 0; nn < 2; nn++) {
                        int ni = 2 * ch + nn;
                        int c0 = nb + ni * 8 + tig * 2;
                        float vv0 = vs[c0], vv1 = vs[c0 + 1];
                        float cc0 = cs[c0], cc1 = cs[c0 + 1];
                        s0m[mi] += vv0 * fast_tanh(accF[mi][ni][0] + cc0)
                                 + vv1 * fast_tanh(accF[mi][ni][1] + cc1);
                        s1m[mi] += vv0 * fast_tanh(accF[mi][ni][2] + cc0)
                                 + vv1 * fast_tanh(accF[mi][ni][3] + cc1);
#pragma unroll
                        for (int j = 0; j < 4; j++) accF[mi][ni][j] = 0.f;
                    }
                }
                if (has_next) {
#pragma unroll
                    for (int jj = 0; jj < 4; jj++) {
                        float4 f0 = fr[2 * jj], f1 = fr[2 * jj + 1];
                        uint32_t h0 = pack_f16(f0.x, f0.y);
                        uint32_t h1 = pack_f16(f0.z, f0.w);
                        uint32_t h2 = pack_f16(f1.x, f1.y);
                        uint32_t h3 = pack_f16(f1.z, f1.w);
                        uint32_t wd = awbase + (uint32_t)(ch * 4 + jj) * 4;
                        sts128(S + SA_HI + ((wd ^ asz) << 2), h0, h1, h2, h3);
                    }
                }
            }
#pragma unroll
            for (int mi = 0; mi < 2; mi++) {
                float s0 = s0m[mi], s1 = s1m[mi];
                s0 += __shfl_xor_sync(0xffffffffu, s0, 1);
                s0 += __shfl_xor_sync(0xffffffffu, s0, 2);
                s1 += __shfl_xor_sync(0xffffffffu, s1, 1);
                s1 += __shfl_xor_sync(0xffffffffu, s1, 2);
                if (tig == 0) {
                    int r0 = mbase + mi * 16 + grp;
                    slog[r0 * 2 + (w >> 2)]       += s0;
                    slog[(r0 + 8) * 2 + (w >> 2)] += s1;
                }
            }
        }
        __syncthreads();

        // ---- finalize logits, per-tile softmax stats ----
        float logit = 0.f;
        if (t < 128) {
            logit = slog[t * 2] + slog[t * 2 + 1];
            attn[rowbase + t] = logit;
            float m = logit;
#pragma unroll
            for (int off = 16; off > 0; off >>= 1)
                m = fmaxf(m, __shfl_xor_sync(0xffffffffu, m, off));
            if (lane == 0) redm[t >> 5] = m;
        }
        __syncthreads();
        float m_tile = fmaxf(fmaxf(redm[0], redm[1]), fmaxf(redm[2], redm[3]));
        if (t < 128) {
            float e = __expf(logit - m_tile);
            es[t] = e;
            float se = e;
#pragma unroll
            for (int off = 16; off > 0; off >>= 1)
                se += __shfl_xor_sync(0xffffffffu, se, off);
            if (lane == 0) reds[t >> 5] = se;
        }
        __syncthreads();   // publishes es[] to all threads
        if (t == 0) {
            g_msum[tile * 2]     = m_tile;
            g_msum[tile * 2 + 1] = (reds[0] + reds[1]) + (reds[2] + reds[3]);
        }

        // ---- partial context from GLOBAL fp32 enc (L2-hot): num = sum e_s*enc ----
        {
            int h4 = t & 63, sg = t >> 6;
            const float4* e4 = (const float4*)(enc + rowbase * HID);
            float4 a4 = make_float4(0.f, 0.f, 0.f, 0.f);
#pragma unroll 4
            for (int s = sg; s < 128; s += 4) {
                float e = es[s];
                float4 x = e4[(size_t)s * 64 + h4];
                a4.x += e * x.x; a4.y += e * x.y;
                a4.z += e * x.z; a4.w += e * x.w;
            }
            float4* comb = (float4*)(smem + SCOMB);
            comb[t] = a4;
            __syncthreads();
            if (t < 64) {
                float4 a = comb[t], bq = comb[t + 64], c = comb[t + 128], d = comb[t + 192];
                float4 r;
                r.x = (a.x + bq.x) + (c.x + d.x);
                r.y = (a.y + bq.y) + (c.y + d.y);
                r.z = (a.z + bq.z) + (c.z + d.z);
                r.w = (a.w + bq.w) + (c.w + d.w);
                ((float4*)(g_pctx + (size_t)tile * HID))[t] = r;
            }
        }
        // next loop-top barrier publishes the already-written next A plane
    }
}

// ---------------------------------------------------------------------------
// finalize: grid (NB, 8) x 256. Each block computes (M, D) from the 64
// per-tile stats by parallel reduce, normalizes its 1/8 slice of attn;
// y==0 blocks also combine partial contexts.
// NOTE: exact same (M,D) math in every block -> bitwise-consistent results.
// ---------------------------------------------------------------------------
__global__ void finalize_kernel(float* __restrict__ attn, float* __restrict__ ctx) {
    __shared__ float sm[64], ss[64], sc[64];
    __shared__ float red[64];
    __shared__ float sMD[2];
    int b = blockIdx.x;
    int seg = blockIdx.y;
    int t = threadIdx.x;   // 256

    if (t < 64) {
        sm[t] = g_msum[(b * 64 + t) * 2];
        ss[t] = g_msum[(b * 64 + t) * 2 + 1];
        red[t] = sm[t];
    }
    __syncthreads();
    if (t < 32) red[t] = fmaxf(red[t], red[t + 32]);
    __syncthreads();
    if (t == 0) {
        float M = red[0];
#pragma unroll
        for (int i = 1; i < 32; i++) M = fmaxf(M, red[i]);
        sMD[0] = M;
    }
    __syncthreads();
    float M = sMD[0];
    if (t < 64) {
        float sci = __expf(sm[t] - M);
        sc[t] = sci;
        red[t] = sci * ss[t];
    }
    __syncthreads();
    if (t == 0) {
        float D = 0.f;
#pragma unroll
        for (int i = 0; i < 64; i++) D += red[i];
        sMD[1] = __fdividef(1.f, D);
    }
    __syncthreads();
    float invD = sMD[1];

    // normalize this block's 1024-logit slice
    float4* row = (float4*)(attn + (size_t)b * NS + (size_t)seg * (NS / 8));
    {
        float4 x = row[t];
        x.x = __expf(x.x - M) * invD;
        x.y = __expf(x.y - M) * invD;
        x.z = __expf(x.z - M) * invD;
        x.w = __expf(x.w - M) * invD;
        row[t] = x;
    }

    // ctx combine (one block per batch)
    if (seg == 0) {
        float acc = 0.f;
#pragma unroll 8
        for (int i = 0; i < 64; i++)
            acc += sc[i] * invD * g_pctx[(size_t)(b * 64 + i) * HID + t];
        ctx[b * HID + t] = acc;
    }
}

// ---------------------------------------------------------------------------
extern "C" void kernel_launch(void* const* d_in, const int* in_sizes, int n_in,
                              void* d_out, int out_size) {
    const float* hidden = (const float*)d_in[0];  // (1,32,256)
    const float* enc    = (const float*)d_in[1];  // (32,8192,256)
    const float* W      = (const float*)d_in[2];  // (256,512)
    const float* bias   = (const float*)d_in[3];  // (256,)
    const float* v      = (const float*)d_in[4];  // (256,)

    float* out  = (float*)d_out;
    float* ctx  = out;            // (32,256) first
    float* attn = out + NB * HID; // (32,8192) second

    cudaFuncSetAttribute(main_mma_kernel,
                         cudaFuncAttributeMaxDynamicSharedMemorySize, SMEM_MAIN);

    prep_kernel<<<160, 256>>>(W, hidden, bias);
    main_mma_kernel<<<GRID_MAIN, 256, SMEM_MAIN>>>(enc, v, attn);
    finalize_kernel<<<dim3(NB, 8), 256>>>(attn, ctx);
}